// round 9
// baseline (speedup 1.0000x reference)
#include <cuda_runtime.h>
#include <cuda_bf16.h>
#include <math.h>
#include <stdint.h>

// Problem constants
#define B_SZ   8
#define T_LEN  1024
#define C_DIM  1024
#define H_NUM  16
#define D_HEAD 64
#define BH     (B_SZ * H_NUM)        // 128
#define M_ROWS (B_SZ * T_LEN)        // 8192
#define K_DIM  1024

// fp32 scratch (pre-rotary q/k only)
__device__ float g_q[BH * T_LEN * D_HEAD];
__device__ float g_k[BH * T_LEN * D_HEAD];

// bf16 hi/lo split buffers
__device__ __nv_bfloat16 g_xhi[M_ROWS * K_DIM];
__device__ __nv_bfloat16 g_xlo[M_ROWS * K_DIM];
__device__ __nv_bfloat16 g_wahi[3 * C_DIM * K_DIM];
__device__ __nv_bfloat16 g_walo[3 * C_DIM * K_DIM];
__device__ __nv_bfloat16 g_wphi[C_DIM * K_DIM];
__device__ __nv_bfloat16 g_wplo[C_DIM * K_DIM];
__device__ __nv_bfloat16 g_qhi[BH * T_LEN * D_HEAD];
__device__ __nv_bfloat16 g_qlo[BH * T_LEN * D_HEAD];
__device__ __nv_bfloat16 g_khi[BH * T_LEN * D_HEAD];
__device__ __nv_bfloat16 g_klo[BH * T_LEN * D_HEAD];
__device__ __nv_bfloat16 g_vhi[BH * T_LEN * D_HEAD];
__device__ __nv_bfloat16 g_vlo[BH * T_LEN * D_HEAD];
__device__ __nv_bfloat16 g_yhi[M_ROWS * C_DIM];
__device__ __nv_bfloat16 g_ylo[M_ROWS * C_DIM];

// ---------------------------------------------------------------------------
// helpers
// ---------------------------------------------------------------------------
__device__ __forceinline__ uint32_t smem_u32(const void* p) {
    uint32_t a;
    asm("{ .reg .u64 t; cvta.to.shared.u64 t, %1; cvt.u32.u64 %0, t; }"
        : "=r"(a) : "l"(p));
    return a;
}
__device__ __forceinline__ void cp16(uint32_t dst, const void* src) {
    asm volatile("cp.async.cg.shared.global [%0], [%1], 16;" :: "r"(dst), "l"(src));
}
__device__ __forceinline__ void cp_commit() {
    asm volatile("cp.async.commit_group;" ::: "memory");
}
__device__ __forceinline__ void cp_wait1() {
    asm volatile("cp.async.wait_group 1;" ::: "memory");
}
__device__ __forceinline__ void cp_wait0() {
    asm volatile("cp.async.wait_group 0;" ::: "memory");
}
__device__ __forceinline__ void ldmat4(uint32_t* r, uint32_t addr) {
    asm volatile("ldmatrix.sync.aligned.m8n8.x4.shared.b16 {%0,%1,%2,%3}, [%4];"
                 : "=r"(r[0]), "=r"(r[1]), "=r"(r[2]), "=r"(r[3]) : "r"(addr));
}
__device__ __forceinline__ void ldmat2(uint32_t* r, uint32_t addr) {
    asm volatile("ldmatrix.sync.aligned.m8n8.x2.shared.b16 {%0,%1}, [%2];"
                 : "=r"(r[0]), "=r"(r[1]) : "r"(addr));
}
__device__ __forceinline__ void ldmat2t(uint32_t* r, uint32_t addr) {
    asm volatile("ldmatrix.sync.aligned.m8n8.x2.trans.shared.b16 {%0,%1}, [%2];"
                 : "=r"(r[0]), "=r"(r[1]) : "r"(addr));
}
__device__ __forceinline__ void mma16816(float* c, const uint32_t* a, const uint32_t* b) {
    asm volatile(
        "mma.sync.aligned.m16n8k16.row.col.f32.bf16.bf16.f32 "
        "{%0,%1,%2,%3}, {%4,%5,%6,%7}, {%8,%9}, {%0,%1,%2,%3};"
        : "+f"(c[0]), "+f"(c[1]), "+f"(c[2]), "+f"(c[3])
        : "r"(a[0]), "r"(a[1]), "r"(a[2]), "r"(a[3]), "r"(b[0]), "r"(b[1]));
}
__device__ __forceinline__ uint32_t packbf(float a, float b) {
    uint32_t r;
    asm("cvt.rn.bf16x2.f32 %0, %1, %2;" : "=r"(r) : "f"(b), "f"(a));
    return r;
}
__device__ __forceinline__ float qmax(float x) {
    x = fmaxf(x, __shfl_xor_sync(0xffffffffu, x, 1));
    x = fmaxf(x, __shfl_xor_sync(0xffffffffu, x, 2));
    return x;
}
__device__ __forceinline__ float qsum(float x) {
    x += __shfl_xor_sync(0xffffffffu, x, 1);
    x += __shfl_xor_sync(0xffffffffu, x, 2);
    return x;
}

// ---------------------------------------------------------------------------
// fp32 -> (bf16 hi, bf16 lo) split
// ---------------------------------------------------------------------------
__global__ __launch_bounds__(256) void split_kernel(const float* __restrict__ src,
                                                    __nv_bfloat16* __restrict__ hi,
                                                    __nv_bfloat16* __restrict__ lo,
                                                    int n4) {
    int i = blockIdx.x * blockDim.x + threadIdx.x;
    if (i >= n4) return;
    float4 x = ((const float4*)src)[i];
    float xs[4] = {x.x, x.y, x.z, x.w};
    __nv_bfloat16 h[4], l[4];
#pragma unroll
    for (int e = 0; e < 4; e++) {
        h[e] = __float2bfloat16(xs[e]);
        l[e] = __float2bfloat16(xs[e] - __bfloat162float(h[e]));
    }
    ((uint2*)hi)[i] = *(uint2*)h;
    ((uint2*)lo)[i] = *(uint2*)l;
}

// ---------------------------------------------------------------------------
// mma.sync bf16x3 GEMM: BM=128, BN templated (96 for QKV -> 7 full waves;
// 128 for proj), BK=32, 2 CTAs/SM.
// ---------------------------------------------------------------------------
#define GSKB 80                       // bytes per 32-bf16 row

template <int MODE, int BN>
__global__ __launch_bounds__(256, 2) void gemm_mma(
    const __nv_bfloat16* __restrict__ Ahi, const __nv_bfloat16* __restrict__ Alo,
    const __nv_bfloat16* __restrict__ Bhi, const __nv_bfloat16* __restrict__ Blo,
    float* __restrict__ Cout) {
    constexpr int NI      = BN / 32;              // per-warp 8-wide n tiles
    constexpr uint32_t OFF_ALO = 128 * GSKB;      // 10240
    constexpr uint32_t OFF_BHI = 2 * 128 * GSKB;  // 20480
    constexpr uint32_t OFF_BLO = OFF_BHI + BN * GSKB;
    constexpr uint32_t BUFSZ   = OFF_BHI + 2 * BN * GSKB;
    constexpr int NITER  = (256 + 2 * BN) * 4 / 256;  // 7 (BN=96) or 8 (BN=128)

    extern __shared__ char dsm[];
    const uint32_t sbase = smem_u32(dsm);

    const int tid  = threadIdx.x;
    const int lane = tid & 31;
    const int wid  = tid >> 5;
    const int wm   = (wid & 1) * 64;
    const int wn   = (wid >> 1) * (BN / 4);
    const int bn   = blockIdx.x * BN;
    const int bm   = blockIdx.y * 128;

    float c[4][NI][4];
#pragma unroll
    for (int mi = 0; mi < 4; mi++)
#pragma unroll
        for (int ni = 0; ni < NI; ni++)
#pragma unroll
            for (int e = 0; e < 4; e++) c[mi][ni][e] = 0.f;

    // flat loader: rows [0,128)=Ahi, [128,256)=Alo, [256,256+BN)=Bhi, rest=Blo
    auto issue = [&](int ch, int buf) {
        const int k0 = ch * 32;
        const uint32_t bb = sbase + (uint32_t)buf * BUFSZ;
#pragma unroll
        for (int it = 0; it < NITER; it++) {
            const int idx = tid + it * 256;
            const int row = idx >> 2;
            const int seg = idx & 3;
            const __nv_bfloat16* src;
            int gb, r;
            uint32_t dst;
            if (row < 128)      { src = Ahi; gb = bm; r = row;       dst = bb + (uint32_t)r * GSKB; }
            else if (row < 256) { src = Alo; gb = bm; r = row - 128; dst = bb + OFF_ALO + (uint32_t)r * GSKB; }
            else if (row < 256 + BN) { src = Bhi; gb = bn; r = row - 256; dst = bb + OFF_BHI + (uint32_t)r * GSKB; }
            else                { src = Blo; gb = bn; r = row - 256 - BN; dst = bb + OFF_BLO + (uint32_t)r * GSKB; }
            cp16(dst + seg * 16, src + (size_t)(gb + r) * K_DIM + k0 + seg * 8);
        }
        cp_commit();
    };

    issue(0, 0);

    const int arow = lane & 15;
    const int acol = (lane >> 4) << 3;
    const int brow = lane & 7;
    const int bcol = ((lane >> 3) & 1) << 3;

    for (int ch = 0; ch < 32; ch++) {
        cp_wait0();
        __syncthreads();
        if (ch < 31) issue(ch + 1, (ch + 1) & 1);

        const uint32_t bb = sbase + (uint32_t)((ch & 1)) * BUFSZ;
        const uint32_t abase = bb;
        const uint32_t bbase = bb + OFF_BHI;

#pragma unroll
        for (int k16 = 0; k16 < 2; k16++) {
            uint32_t bh[NI][2], bl[NI][2];
#pragma unroll
            for (int ni = 0; ni < NI; ni++) {
                const uint32_t bd = bbase + (uint32_t)(wn + ni * 8 + brow) * GSKB
                                  + (uint32_t)(k16 * 16 + bcol) * 2;
                ldmat2(bh[ni], bd);
                ldmat2(bl[ni], bd + BN * GSKB);
            }
#pragma unroll
            for (int mi = 0; mi < 4; mi++) {
                uint32_t ah[4], al[4];
                const uint32_t ad = abase + (uint32_t)(wm + mi * 16 + arow) * GSKB
                                  + (uint32_t)(k16 * 16 + acol) * 2;
                ldmat4(ah, ad);
                ldmat4(al, ad + OFF_ALO);
#pragma unroll
                for (int ni = 0; ni < NI; ni++) {
                    mma16816(c[mi][ni], ah, bh[ni]);
                    mma16816(c[mi][ni], ah, bl[ni]);
                    mma16816(c[mi][ni], al, bh[ni]);
                }
            }
        }
    }

    const int g  = lane >> 2;
    const int tg = lane & 3;
#pragma unroll
    for (int mi = 0; mi < 4; mi++) {
#pragma unroll
        for (int ni = 0; ni < NI; ni++) {
            const int n = bn + wn + ni * 8 + 2 * tg;
            const int m0r = bm + wm + mi * 16 + g;
            if (MODE == 0) {
                const int part = n >> 10;
                const int cc = n & 1023;
                const int h = cc >> 6;
                const int d = cc & 63;
#pragma unroll
                for (int rr = 0; rr < 2; rr++) {
                    const int m = m0r + rr * 8;
                    const int b = m >> 10;
                    const int t = m & 1023;
                    const size_t off = ((size_t)(b * 16 + h) * T_LEN + t) * D_HEAD + d;
                    float2 v = rr ? make_float2(c[mi][ni][2], c[mi][ni][3])
                                  : make_float2(c[mi][ni][0], c[mi][ni][1]);
                    if (part == 0)      *(float2*)(g_q + off) = v;
                    else if (part == 1) *(float2*)(g_k + off) = v;
                    else {
                        uint32_t hi = packbf(v.x, v.y);
                        float hx = __bfloat162float(__float2bfloat16(v.x));
                        float hy = __bfloat162float(__float2bfloat16(v.y));
                        uint32_t lo = packbf(v.x - hx, v.y - hy);
                        *(uint32_t*)(g_vhi + off) = hi;
                        *(uint32_t*)(g_vlo + off) = lo;
                    }
                }
            } else {
                *(float2*)(Cout + (size_t)m0r * C_DIM + n) =
                    make_float2(c[mi][ni][0], c[mi][ni][1]);
                *(float2*)(Cout + (size_t)(m0r + 8) * C_DIM + n) =
                    make_float2(c[mi][ni][2], c[mi][ni][3]);
            }
        }
    }
}

#define DSMEM_G0 (2 * (20480 + 2 * 96 * GSKB))    // 71680 (BN=96)
#define DSMEM_G1 (2 * (20480 + 2 * 128 * GSKB))   // 81920 (BN=128)

// ---------------------------------------------------------------------------
// Rotary: fast __sincosf
// ---------------------------------------------------------------------------
__global__ __launch_bounds__(256) void rotary_kernel() {
    const int idx = blockIdx.x * blockDim.x + threadIdx.x;
    if (idx >= BH * T_LEN) return;
    const float* qp = g_q + (size_t)idx * D_HEAD;
    const float* kp = g_k + (size_t)idx * D_HEAD;

    float q[64], k[64];
#pragma unroll
    for (int i = 0; i < 16; i++) {
        ((float4*)q)[i] = ((const float4*)qp)[i];
        ((float4*)k)[i] = ((const float4*)kp)[i];
    }
    uint32_t* qh32 = (uint32_t*)g_qhi + (size_t)idx * 32;
    uint32_t* ql32 = (uint32_t*)g_qlo + (size_t)idx * 32;
    uint32_t* kh32 = (uint32_t*)g_khi + (size_t)idx * 32;
    uint32_t* kl32 = (uint32_t*)g_klo + (size_t)idx * 32;

#pragma unroll
    for (int i = 0; i < 32; i++) {
        float qo[2], ko[2];
#pragma unroll
        for (int e = 0; e < 2; e++) {
            const int d = 2 * i + e;
            float cc, sn;
            __sincosf(q[d], &sn, &cc);
            const float rq = (d < 32) ? -q[2 * d + 1] : q[2 * d - 64];
            const float rk = (d < 32) ? -k[2 * d + 1] : k[2 * d - 64];
            qo[e] = q[d] * cc + rq * sn;
            ko[e] = k[d] * cc + rk * sn;
        }
        qh32[i] = packbf(qo[0], qo[1]);
        ql32[i] = packbf(qo[0] - __bfloat162float(__float2bfloat16(qo[0])),
                         qo[1] - __bfloat162float(__float2bfloat16(qo[1])));
        kh32[i] = packbf(ko[0], ko[1]);
        kl32[i] = packbf(ko[0] - __bfloat162float(__float2bfloat16(ko[0])),
                         ko[1] - __bfloat162float(__float2bfloat16(ko[1])));
    }
}

// ---------------------------------------------------------------------------
// Tensor-core flash attention (causal, scale=1.0). Verified round-7 version.
// ---------------------------------------------------------------------------
#define SKE 72
#define SKB (SKE * 2)                // 144
#define ATILE (64 * SKB)             // 9216
#define QTILE (128 * SKB)            // 18432
#define DSMEM_A (2 * QTILE + 8 * ATILE)  // 110592

__global__ __launch_bounds__(256, 1) void attn_mma() {
    extern __shared__ char dsm[];
    const uint32_t sbase = smem_u32(dsm);
    const uint32_t kvbase = sbase + 2 * QTILE;

    const int tid  = threadIdx.x;
    const int lane = tid & 31;
    const int wid  = tid >> 5;
    const int wm   = wid * 16;
    const int bh   = blockIdx.y;
    const int q0   = blockIdx.x * 128;
    const int nt   = 2 * (blockIdx.x + 1);

    {
        const __nv_bfloat16* qs[2] = {g_qhi, g_qlo};
#pragma unroll
        for (int it = 0; it < 8; it++) {
            const int idx = tid + it * 256;
            const int half = idx >> 10;
            const int rem = idx & 1023;
            const int row = rem >> 3;
            const int seg = rem & 7;
            cp16(sbase + (uint32_t)half * QTILE + (uint32_t)row * SKB + seg * 16,
                 qs[half] + ((size_t)(bh * T_LEN + q0 + row) * D_HEAD + seg * 8));
        }
        cp_commit();
    }

    const __nv_bfloat16* kvsrc[4] = {g_khi, g_klo, g_vhi, g_vlo};
    auto issue_kv = [&](int j0, int buf) {
#pragma unroll
        for (int it = 0; it < 8; it++) {
            const int idx = tid + it * 256;
            const int sub = idx >> 9;
            const int rem = idx & 511;
            const int row = rem >> 3;
            const int seg = rem & 7;
            cp16(kvbase + (uint32_t)(buf * 4 + sub) * ATILE + (uint32_t)row * SKB + seg * 16,
                 kvsrc[sub] + ((size_t)(bh * T_LEN + j0 + row) * D_HEAD + seg * 8));
        }
        cp_commit();
    };

    issue_kv(0, 0);

    float o[8][4];
#pragma unroll
    for (int ni = 0; ni < 8; ni++)
#pragma unroll
        for (int e = 0; e < 4; e++) o[ni][e] = 0.f;
    float m0 = -1e30f, m1 = -1e30f, l0 = 0.f, l1 = 0.f;
    uint32_t qh[4][4], ql[4][4];

    const int g  = lane >> 2;
    const int tg = lane & 3;
    const int brow = lane & 7;
    const int bsel = ((lane >> 3) & 1) * 8;

    for (int t = 0; t < nt; t++) {
        const int j0 = t * 64;
        if (t + 1 < nt) { issue_kv((t + 1) * 64, (t + 1) & 1); cp_wait1(); }
        else            { cp_wait0(); }
        __syncthreads();

        if (t == 0) {
            const int arow = lane & 15;
            const int acol = (lane >> 4) << 3;
#pragma unroll
            for (int k16 = 0; k16 < 4; k16++) {
                const uint32_t ad = sbase + (uint32_t)(wm + arow) * SKB
                                  + (uint32_t)(k16 * 16 + acol) * 2;
                ldmat4(qh[k16], ad);
                ldmat4(ql[k16], ad + QTILE);
            }
        }

        const uint32_t kb = kvbase + (uint32_t)((t & 1) * 4) * ATILE;

        float s[8][4];
#pragma unroll
        for (int ni = 0; ni < 8; ni++) {
#pragma unroll
            for (int e = 0; e < 4; e++) s[ni][e] = 0.f;
#pragma unroll
            for (int k16 = 0; k16 < 4; k16++) {
                const uint32_t bd = kb + (uint32_t)(ni * 8 + brow) * SKB
                                  + (uint32_t)(k16 * 16 + bsel) * 2;
                uint32_t kh[2], kl[2];
                ldmat2(kh, bd);
                ldmat2(kl, bd + ATILE);
                mma16816(s[ni], qh[k16], kh);
                mma16816(s[ni], qh[k16], kl);
                mma16816(s[ni], ql[k16], kh);
            }
        }

        if (t >= nt - 2) {
            const int r0 = q0 + wm + g;
#pragma unroll
            for (int ni = 0; ni < 8; ni++) {
                const int cbase = j0 + ni * 8 + 2 * tg;
#pragma unroll
                for (int e = 0; e < 4; e++) {
                    const int col = cbase + (e & 1);
                    const int row = (e < 2) ? r0 : r0 + 8;
                    if (col > row) s[ni][e] = -1e30f;
                }
            }
        }

        float tm0 = -1e30f, tm1 = -1e30f;
#pragma unroll
        for (int ni = 0; ni < 8; ni++) {
            tm0 = fmaxf(tm0, fmaxf(s[ni][0], s[ni][1]));
            tm1 = fmaxf(tm1, fmaxf(s[ni][2], s[ni][3]));
        }
        tm0 = qmax(tm0); tm1 = qmax(tm1);
        const float mn0 = fmaxf(m0, tm0);
        const float mn1 = fmaxf(m1, tm1);
        const float corr0 = __expf(m0 - mn0);
        const float corr1 = __expf(m1 - mn1);
        m0 = mn0; m1 = mn1;

        float ps0 = 0.f, ps1 = 0.f;
#pragma unroll
        for (int ni = 0; ni < 8; ni++) {
            s[ni][0] = __expf(s[ni][0] - m0);
            s[ni][1] = __expf(s[ni][1] - m0);
            s[ni][2] = __expf(s[ni][2] - m1);
            s[ni][3] = __expf(s[ni][3] - m1);
            ps0 += s[ni][0] + s[ni][1];
            ps1 += s[ni][2] + s[ni][3];
        }
        ps0 = qsum(ps0); ps1 = qsum(ps1);
        l0 = l0 * corr0 + ps0;
        l1 = l1 * corr1 + ps1;
#pragma unroll
        for (int ni = 0; ni < 8; ni++) {
            o[ni][0] *= corr0; o[ni][1] *= corr0;
            o[ni][2] *= corr1; o[ni][3] *= corr1;
        }

#pragma unroll
        for (int kj = 0; kj < 4; kj++) {
            uint32_t Ah[4], Al[4];
#pragma unroll
            for (int half = 0; half < 2; half++) {
                const int sn = 2 * kj + half;
                const float p0 = s[sn][0], p1 = s[sn][1];
                const float p2 = s[sn][2], p3 = s[sn][3];
                Ah[2 * half + 0] = packbf(p0, p1);
                Ah[2 * half + 1] = packbf(p2, p3);
                Al[2 * half + 0] = packbf(p0 - __bfloat162float(__float2bfloat16(p0)),
                                          p1 - __bfloat162float(__float2bfloat16(p1)));
                Al[2 * half + 1] = packbf(p2 - __bfloat162float(__float2bfloat16(p2)),
                                          p3 - __bfloat162float(__float2bfloat16(p3)));
            }
            const int vrow = kj * 16 + bsel + brow;
#pragma unroll
            for (int ni = 0; ni < 8; ni++) {
                const uint32_t vd = kb + 2 * ATILE + (uint32_t)vrow * SKB + ni * 16;
                uint32_t vh[2], vl[2];
                ldmat2t(vh, vd);
                ldmat2t(vl, vd + ATILE);
                mma16816(o[ni], Ah, vh);
                mma16816(o[ni], Ah, vl);
                mma16816(o[ni], Al, vh);
            }
        }
        __syncthreads();
    }

    const float inv0 = 1.f / l0;
    const float inv1 = 1.f / l1;
    const int b = bh >> 4;
    const int h = bh & 15;
    const int r0 = q0 + wm + g;
#pragma unroll
    for (int ni = 0; ni < 8; ni++) {
        const int d = ni * 8 + 2 * tg;
#pragma unroll
        for (int rr = 0; rr < 2; rr++) {
            const int row = r0 + rr * 8;
            const float y0 = o[ni][2 * rr + 0] * (rr ? inv1 : inv0);
            const float y1 = o[ni][2 * rr + 1] * (rr ? inv1 : inv0);
            const size_t off = (size_t)(b * T_LEN + row) * C_DIM + h * D_HEAD + d;
            *(uint32_t*)(g_yhi + off) = packbf(y0, y1);
            *(uint32_t*)(g_ylo + off) =
                packbf(y0 - __bfloat162float(__float2bfloat16(y0)),
                       y1 - __bfloat162float(__float2bfloat16(y1)));
        }
    }
}

// ---------------------------------------------------------------------------
extern "C" void kernel_launch(void* const* d_in, const int* in_sizes, int n_in,
                              void* d_out, int out_size) {
    const float* x  = (const float*)d_in[0];   // (8,1024,1024)
    const float* Wa = (const float*)d_in[1];   // (3072,1024)
    const float* Wp = (const float*)d_in[2];   // (1024,1024)
    float* out = (float*)d_out;                // (8,1024,1024)

    cudaFuncSetAttribute(gemm_mma<0, 96>,  cudaFuncAttributeMaxDynamicSharedMemorySize, DSMEM_G0);
    cudaFuncSetAttribute(gemm_mma<1, 128>, cudaFuncAttributeMaxDynamicSharedMemorySize, DSMEM_G1);
    cudaFuncSetAttribute(attn_mma, cudaFuncAttributeMaxDynamicSharedMemorySize, DSMEM_A);

    __nv_bfloat16 *xhi, *xlo, *wahi, *walo, *wphi, *wplo, *yhi, *ylo;
    cudaGetSymbolAddress((void**)&xhi,  g_xhi);
    cudaGetSymbolAddress((void**)&xlo,  g_xlo);
    cudaGetSymbolAddress((void**)&wahi, g_wahi);
    cudaGetSymbolAddress((void**)&walo, g_walo);
    cudaGetSymbolAddress((void**)&wphi, g_wphi);
    cudaGetSymbolAddress((void**)&wplo, g_wplo);
    cudaGetSymbolAddress((void**)&yhi,  g_yhi);
    cudaGetSymbolAddress((void**)&ylo,  g_ylo);

    split_kernel<<<(M_ROWS * K_DIM / 4) / 256, 256>>>(x,  xhi,  xlo,  M_ROWS * K_DIM / 4);
    split_kernel<<<(3 * C_DIM * K_DIM / 4) / 256, 256>>>(Wa, wahi, walo, 3 * C_DIM * K_DIM / 4);
    split_kernel<<<(C_DIM * K_DIM / 4) / 256, 256>>>(Wp, wphi, wplo, C_DIM * K_DIM / 4);

    // QKV: BN=96 -> grid 32x64 = 2048 CTAs = 6.92 occupancy-waves (no tail)
    gemm_mma<0, 96><<<dim3(3072 / 96, M_ROWS / 128), 256, DSMEM_G0>>>(xhi, xlo, wahi, walo, nullptr);

    rotary_kernel<<<(BH * T_LEN) / 256, 256>>>();

    attn_mma<<<dim3(T_LEN / 128, BH), 256, DSMEM_A>>>();

    gemm_mma<1, 128><<<dim3(1024 / 128, M_ROWS / 128), 256, DSMEM_G1>>>(yhi, ylo, wphi, wplo, out);
}

// round 10
// speedup vs baseline: 1.0039x; 1.0039x over previous
#include <cuda_runtime.h>
#include <cuda_bf16.h>
#include <math.h>
#include <stdint.h>

// Problem constants
#define B_SZ   8
#define T_LEN  1024
#define C_DIM  1024
#define H_NUM  16
#define D_HEAD 64
#define BH     (B_SZ * H_NUM)        // 128
#define M_ROWS (B_SZ * T_LEN)        // 8192
#define K_DIM  1024

// fp32 scratch (pre-rotary q/k only)
__device__ float g_q[BH * T_LEN * D_HEAD];
__device__ float g_k[BH * T_LEN * D_HEAD];

// bf16 hi/lo split buffers
__device__ __nv_bfloat16 g_xhi[M_ROWS * K_DIM];
__device__ __nv_bfloat16 g_xlo[M_ROWS * K_DIM];
__device__ __nv_bfloat16 g_wahi[3 * C_DIM * K_DIM];
__device__ __nv_bfloat16 g_walo[3 * C_DIM * K_DIM];
__device__ __nv_bfloat16 g_wphi[C_DIM * K_DIM];
__device__ __nv_bfloat16 g_wplo[C_DIM * K_DIM];
__device__ __nv_bfloat16 g_qhi[BH * T_LEN * D_HEAD];
__device__ __nv_bfloat16 g_qlo[BH * T_LEN * D_HEAD];
__device__ __nv_bfloat16 g_khi[BH * T_LEN * D_HEAD];
__device__ __nv_bfloat16 g_klo[BH * T_LEN * D_HEAD];
__device__ __nv_bfloat16 g_vhi[BH * T_LEN * D_HEAD];
__device__ __nv_bfloat16 g_vlo[BH * T_LEN * D_HEAD];
__device__ __nv_bfloat16 g_yhi[M_ROWS * C_DIM];
__device__ __nv_bfloat16 g_ylo[M_ROWS * C_DIM];

// ---------------------------------------------------------------------------
// helpers
// ---------------------------------------------------------------------------
__device__ __forceinline__ uint32_t smem_u32(const void* p) {
    uint32_t a;
    asm("{ .reg .u64 t; cvta.to.shared.u64 t, %1; cvt.u32.u64 %0, t; }"
        : "=r"(a) : "l"(p));
    return a;
}
__device__ __forceinline__ void cp16(uint32_t dst, const void* src) {
    asm volatile("cp.async.cg.shared.global [%0], [%1], 16;" :: "r"(dst), "l"(src));
}
__device__ __forceinline__ void cp_commit() {
    asm volatile("cp.async.commit_group;" ::: "memory");
}
__device__ __forceinline__ void cp_wait1() {
    asm volatile("cp.async.wait_group 1;" ::: "memory");
}
__device__ __forceinline__ void cp_wait0() {
    asm volatile("cp.async.wait_group 0;" ::: "memory");
}
__device__ __forceinline__ void ldmat4(uint32_t* r, uint32_t addr) {
    asm volatile("ldmatrix.sync.aligned.m8n8.x4.shared.b16 {%0,%1,%2,%3}, [%4];"
                 : "=r"(r[0]), "=r"(r[1]), "=r"(r[2]), "=r"(r[3]) : "r"(addr));
}
__device__ __forceinline__ void ldmat2(uint32_t* r, uint32_t addr) {
    asm volatile("ldmatrix.sync.aligned.m8n8.x2.shared.b16 {%0,%1}, [%2];"
                 : "=r"(r[0]), "=r"(r[1]) : "r"(addr));
}
__device__ __forceinline__ void ldmat4t(uint32_t* r, uint32_t addr) {
    asm volatile("ldmatrix.sync.aligned.m8n8.x4.trans.shared.b16 {%0,%1,%2,%3}, [%4];"
                 : "=r"(r[0]), "=r"(r[1]), "=r"(r[2]), "=r"(r[3]) : "r"(addr));
}
__device__ __forceinline__ void mma16816(float* c, const uint32_t* a, const uint32_t* b) {
    asm volatile(
        "mma.sync.aligned.m16n8k16.row.col.f32.bf16.bf16.f32 "
        "{%0,%1,%2,%3}, {%4,%5,%6,%7}, {%8,%9}, {%0,%1,%2,%3};"
        : "+f"(c[0]), "+f"(c[1]), "+f"(c[2]), "+f"(c[3])
        : "r"(a[0]), "r"(a[1]), "r"(a[2]), "r"(a[3]), "r"(b[0]), "r"(b[1]));
}
__device__ __forceinline__ uint32_t packbf(float a, float b) {
    uint32_t r;
    asm("cvt.rn.bf16x2.f32 %0, %1, %2;" : "=r"(r) : "f"(b), "f"(a));
    return r;
}
__device__ __forceinline__ float qmax(float x) {
    x = fmaxf(x, __shfl_xor_sync(0xffffffffu, x, 1));
    x = fmaxf(x, __shfl_xor_sync(0xffffffffu, x, 2));
    return x;
}
__device__ __forceinline__ float qsum(float x) {
    x += __shfl_xor_sync(0xffffffffu, x, 1);
    x += __shfl_xor_sync(0xffffffffu, x, 2);
    return x;
}

// ---------------------------------------------------------------------------
// fp32 -> (bf16 hi, bf16 lo) split
// ---------------------------------------------------------------------------
__global__ __launch_bounds__(256) void split_kernel(const float* __restrict__ src,
                                                    __nv_bfloat16* __restrict__ hi,
                                                    __nv_bfloat16* __restrict__ lo,
                                                    int n4) {
    int i = blockIdx.x * blockDim.x + threadIdx.x;
    if (i >= n4) return;
    float4 x = ((const float4*)src)[i];
    float xs[4] = {x.x, x.y, x.z, x.w};
    __nv_bfloat16 h[4], l[4];
#pragma unroll
    for (int e = 0; e < 4; e++) {
        h[e] = __float2bfloat16(xs[e]);
        l[e] = __float2bfloat16(xs[e] - __bfloat162float(h[e]));
    }
    ((uint2*)hi)[i] = *(uint2*)h;
    ((uint2*)lo)[i] = *(uint2*)l;
}

// ---------------------------------------------------------------------------
// mma.sync bf16x3 GEMM: BM=128, BN=128, BK=32, 2 CTAs/SM (R7 verified config)
// ---------------------------------------------------------------------------
#define GSKB 80                       // bytes per 32-bf16 row

template <int MODE, int BN>
__global__ __launch_bounds__(256, 2) void gemm_mma(
    const __nv_bfloat16* __restrict__ Ahi, const __nv_bfloat16* __restrict__ Alo,
    const __nv_bfloat16* __restrict__ Bhi, const __nv_bfloat16* __restrict__ Blo,
    float* __restrict__ Cout) {
    constexpr int NI      = BN / 32;
    constexpr uint32_t OFF_ALO = 128 * GSKB;
    constexpr uint32_t OFF_BHI = 2 * 128 * GSKB;
    constexpr uint32_t OFF_BLO = OFF_BHI + BN * GSKB;
    constexpr uint32_t BUFSZ   = OFF_BHI + 2 * BN * GSKB;
    constexpr int NITER  = (256 + 2 * BN) * 4 / 256;

    extern __shared__ char dsm[];
    const uint32_t sbase = smem_u32(dsm);

    const int tid  = threadIdx.x;
    const int lane = tid & 31;
    const int wid  = tid >> 5;
    const int wm   = (wid & 1) * 64;
    const int wn   = (wid >> 1) * (BN / 4);
    const int bn   = blockIdx.x * BN;
    const int bm   = blockIdx.y * 128;

    float c[4][NI][4];
#pragma unroll
    for (int mi = 0; mi < 4; mi++)
#pragma unroll
        for (int ni = 0; ni < NI; ni++)
#pragma unroll
            for (int e = 0; e < 4; e++) c[mi][ni][e] = 0.f;

    auto issue = [&](int ch, int buf) {
        const int k0 = ch * 32;
        const uint32_t bb = sbase + (uint32_t)buf * BUFSZ;
#pragma unroll
        for (int it = 0; it < NITER; it++) {
            const int idx = tid + it * 256;
            const int row = idx >> 2;
            const int seg = idx & 3;
            const __nv_bfloat16* src;
            int gb, r;
            uint32_t dst;
            if (row < 128)      { src = Ahi; gb = bm; r = row;       dst = bb + (uint32_t)r * GSKB; }
            else if (row < 256) { src = Alo; gb = bm; r = row - 128; dst = bb + OFF_ALO + (uint32_t)r * GSKB; }
            else if (row < 256 + BN) { src = Bhi; gb = bn; r = row - 256; dst = bb + OFF_BHI + (uint32_t)r * GSKB; }
            else                { src = Blo; gb = bn; r = row - 256 - BN; dst = bb + OFF_BLO + (uint32_t)r * GSKB; }
            cp16(dst + seg * 16, src + (size_t)(gb + r) * K_DIM + k0 + seg * 8);
        }
        cp_commit();
    };

    issue(0, 0);

    const int arow = lane & 15;
    const int acol = (lane >> 4) << 3;
    const int brow = lane & 7;
    const int bcol = ((lane >> 3) & 1) << 3;

    for (int ch = 0; ch < 32; ch++) {
        cp_wait0();
        __syncthreads();
        if (ch < 31) issue(ch + 1, (ch + 1) & 1);

        const uint32_t bb = sbase + (uint32_t)((ch & 1)) * BUFSZ;
        const uint32_t abase = bb;
        const uint32_t bbase = bb + OFF_BHI;

#pragma unroll
        for (int k16 = 0; k16 < 2; k16++) {
            uint32_t bh[NI][2], bl[NI][2];
#pragma unroll
            for (int ni = 0; ni < NI; ni++) {
                const uint32_t bd = bbase + (uint32_t)(wn + ni * 8 + brow) * GSKB
                                  + (uint32_t)(k16 * 16 + bcol) * 2;
                ldmat2(bh[ni], bd);
                ldmat2(bl[ni], bd + BN * GSKB);
            }
#pragma unroll
            for (int mi = 0; mi < 4; mi++) {
                uint32_t ah[4], al[4];
                const uint32_t ad = abase + (uint32_t)(wm + mi * 16 + arow) * GSKB
                                  + (uint32_t)(k16 * 16 + acol) * 2;
                ldmat4(ah, ad);
                ldmat4(al, ad + OFF_ALO);
#pragma unroll
                for (int ni = 0; ni < NI; ni++) {
                    mma16816(c[mi][ni], ah, bh[ni]);
                    mma16816(c[mi][ni], ah, bl[ni]);
                    mma16816(c[mi][ni], al, bh[ni]);
                }
            }
        }
    }

    const int g  = lane >> 2;
    const int tg = lane & 3;
#pragma unroll
    for (int mi = 0; mi < 4; mi++) {
#pragma unroll
        for (int ni = 0; ni < NI; ni++) {
            const int n = bn + wn + ni * 8 + 2 * tg;
            const int m0r = bm + wm + mi * 16 + g;
            if (MODE == 0) {
                const int part = n >> 10;
                const int cc = n & 1023;
                const int h = cc >> 6;
                const int d = cc & 63;
#pragma unroll
                for (int rr = 0; rr < 2; rr++) {
                    const int m = m0r + rr * 8;
                    const int b = m >> 10;
                    const int t = m & 1023;
                    const size_t off = ((size_t)(b * 16 + h) * T_LEN + t) * D_HEAD + d;
                    float2 v = rr ? make_float2(c[mi][ni][2], c[mi][ni][3])
                                  : make_float2(c[mi][ni][0], c[mi][ni][1]);
                    if (part == 0)      *(float2*)(g_q + off) = v;
                    else if (part == 1) *(float2*)(g_k + off) = v;
                    else {
                        uint32_t hi = packbf(v.x, v.y);
                        float hx = __bfloat162float(__float2bfloat16(v.x));
                        float hy = __bfloat162float(__float2bfloat16(v.y));
                        uint32_t lo = packbf(v.x - hx, v.y - hy);
                        *(uint32_t*)(g_vhi + off) = hi;
                        *(uint32_t*)(g_vlo + off) = lo;
                    }
                }
            } else {
                *(float2*)(Cout + (size_t)m0r * C_DIM + n) =
                    make_float2(c[mi][ni][0], c[mi][ni][1]);
                *(float2*)(Cout + (size_t)(m0r + 8) * C_DIM + n) =
                    make_float2(c[mi][ni][2], c[mi][ni][3]);
            }
        }
    }
}

#define DSMEM_G (2 * (20480 + 2 * 128 * GSKB))    // 81920 (BN=128)

// ---------------------------------------------------------------------------
// Rotary: fast __sincosf
// ---------------------------------------------------------------------------
__global__ __launch_bounds__(256) void rotary_kernel() {
    const int idx = blockIdx.x * blockDim.x + threadIdx.x;
    if (idx >= BH * T_LEN) return;
    const float* qp = g_q + (size_t)idx * D_HEAD;
    const float* kp = g_k + (size_t)idx * D_HEAD;

    float q[64], k[64];
#pragma unroll
    for (int i = 0; i < 16; i++) {
        ((float4*)q)[i] = ((const float4*)qp)[i];
        ((float4*)k)[i] = ((const float4*)kp)[i];
    }
    uint32_t* qh32 = (uint32_t*)g_qhi + (size_t)idx * 32;
    uint32_t* ql32 = (uint32_t*)g_qlo + (size_t)idx * 32;
    uint32_t* kh32 = (uint32_t*)g_khi + (size_t)idx * 32;
    uint32_t* kl32 = (uint32_t*)g_klo + (size_t)idx * 32;

#pragma unroll
    for (int i = 0; i < 32; i++) {
        float qo[2], ko[2];
#pragma unroll
        for (int e = 0; e < 2; e++) {
            const int d = 2 * i + e;
            float cc, sn;
            __sincosf(q[d], &sn, &cc);
            const float rq = (d < 32) ? -q[2 * d + 1] : q[2 * d - 64];
            const float rk = (d < 32) ? -k[2 * d + 1] : k[2 * d - 64];
            qo[e] = q[d] * cc + rq * sn;
            ko[e] = k[d] * cc + rk * sn;
        }
        qh32[i] = packbf(qo[0], qo[1]);
        ql32[i] = packbf(qo[0] - __bfloat162float(__float2bfloat16(qo[0])),
                         qo[1] - __bfloat162float(__float2bfloat16(qo[1])));
        kh32[i] = packbf(ko[0], ko[1]);
        kl32[i] = packbf(ko[0] - __bfloat162float(__float2bfloat16(ko[0])),
                         ko[1] - __bfloat162float(__float2bfloat16(ko[1])));
    }
}

// ---------------------------------------------------------------------------
// Tensor-core flash attention: x4 ldmatrix for K and V (4x fewer LDSM instrs)
// ---------------------------------------------------------------------------
#define SKE 72
#define SKB (SKE * 2)                // 144
#define ATILE (64 * SKB)             // 9216
#define QTILE (128 * SKB)            // 18432
#define DSMEM_A (2 * QTILE + 8 * ATILE)  // 110592

__global__ __launch_bounds__(256, 1) void attn_mma() {
    extern __shared__ char dsm[];
    const uint32_t sbase = smem_u32(dsm);
    const uint32_t kvbase = sbase + 2 * QTILE;

    const int tid  = threadIdx.x;
    const int lane = tid & 31;
    const int wid  = tid >> 5;
    const int wm   = wid * 16;
    const int bh   = blockIdx.y;
    const int q0   = blockIdx.x * 128;
    const int nt   = 2 * (blockIdx.x + 1);

    {
        const __nv_bfloat16* qs[2] = {g_qhi, g_qlo};
#pragma unroll
        for (int it = 0; it < 8; it++) {
            const int idx = tid + it * 256;
            const int half = idx >> 10;
            const int rem = idx & 1023;
            const int row = rem >> 3;
            const int seg = rem & 7;
            cp16(sbase + (uint32_t)half * QTILE + (uint32_t)row * SKB + seg * 16,
                 qs[half] + ((size_t)(bh * T_LEN + q0 + row) * D_HEAD + seg * 8));
        }
        cp_commit();
    }

    const __nv_bfloat16* kvsrc[4] = {g_khi, g_klo, g_vhi, g_vlo};
    auto issue_kv = [&](int j0, int buf) {
#pragma unroll
        for (int it = 0; it < 8; it++) {
            const int idx = tid + it * 256;
            const int sub = idx >> 9;
            const int rem = idx & 511;
            const int row = rem >> 3;
            const int seg = rem & 7;
            cp16(kvbase + (uint32_t)(buf * 4 + sub) * ATILE + (uint32_t)row * SKB + seg * 16,
                 kvsrc[sub] + ((size_t)(bh * T_LEN + j0 + row) * D_HEAD + seg * 8));
        }
        cp_commit();
    };

    issue_kv(0, 0);

    float o[8][4];
#pragma unroll
    for (int ni = 0; ni < 8; ni++)
#pragma unroll
        for (int e = 0; e < 4; e++) o[ni][e] = 0.f;
    float m0 = -1e30f, m1 = -1e30f, l0 = 0.f, l1 = 0.f;
    uint32_t qh[4][4], ql[4][4];

    const int g  = lane >> 2;
    const int tg = lane & 3;
    const int brow  = lane & 7;
    const int bsel  = ((lane >> 3) & 1) * 8;
    const int klane = (lane >> 4) & 1;      // x4 pair selector (lanes 16-31)
    const int vrow16 = lane & 15;           // V x4t row-within-16

    for (int t = 0; t < nt; t++) {
        const int j0 = t * 64;
        if (t + 1 < nt) { issue_kv((t + 1) * 64, (t + 1) & 1); cp_wait1(); }
        else            { cp_wait0(); }
        __syncthreads();

        if (t == 0) {
            const int arow = lane & 15;
            const int acol = (lane >> 4) << 3;
#pragma unroll
            for (int k16 = 0; k16 < 4; k16++) {
                const uint32_t ad = sbase + (uint32_t)(wm + arow) * SKB
                                  + (uint32_t)(k16 * 16 + acol) * 2;
                ldmat4(qh[k16], ad);
                ldmat4(ql[k16], ad + QTILE);
            }
        }

        const uint32_t kb = kvbase + (uint32_t)((t & 1) * 4) * ATILE;

        // S = Q K^T: x4 ldmatrix loads k16 and k16+1 fragments together
        float s[8][4];
#pragma unroll
        for (int ni = 0; ni < 8; ni++) {
#pragma unroll
            for (int e = 0; e < 4; e++) s[ni][e] = 0.f;
#pragma unroll
            for (int k2 = 0; k2 < 2; k2++) {
                const uint32_t bd = kb + (uint32_t)(ni * 8 + brow) * SKB
                                  + (uint32_t)((2 * k2 + klane) * 16 + bsel) * 2;
                uint32_t kh4[4], kl4[4];
                ldmat4(kh4, bd);
                ldmat4(kl4, bd + ATILE);
                mma16816(s[ni], qh[2 * k2],     kh4);
                mma16816(s[ni], qh[2 * k2],     kl4);
                mma16816(s[ni], ql[2 * k2],     kh4);
                mma16816(s[ni], qh[2 * k2 + 1], kh4 + 2);
                mma16816(s[ni], qh[2 * k2 + 1], kl4 + 2);
                mma16816(s[ni], ql[2 * k2 + 1], kh4 + 2);
            }
        }

        if (t >= nt - 2) {
            const int r0 = q0 + wm + g;
#pragma unroll
            for (int ni = 0; ni < 8; ni++) {
                const int cbase = j0 + ni * 8 + 2 * tg;
#pragma unroll
                for (int e = 0; e < 4; e++) {
                    const int col = cbase + (e & 1);
                    const int row = (e < 2) ? r0 : r0 + 8;
                    if (col > row) s[ni][e] = -1e30f;
                }
            }
        }

        float tm0 = -1e30f, tm1 = -1e30f;
#pragma unroll
        for (int ni = 0; ni < 8; ni++) {
            tm0 = fmaxf(tm0, fmaxf(s[ni][0], s[ni][1]));
            tm1 = fmaxf(tm1, fmaxf(s[ni][2], s[ni][3]));
        }
        tm0 = qmax(tm0); tm1 = qmax(tm1);
        const float mn0 = fmaxf(m0, tm0);
        const float mn1 = fmaxf(m1, tm1);
        const float corr0 = __expf(m0 - mn0);
        const float corr1 = __expf(m1 - mn1);
        m0 = mn0; m1 = mn1;

        float ps0 = 0.f, ps1 = 0.f;
#pragma unroll
        for (int ni = 0; ni < 8; ni++) {
            s[ni][0] = __expf(s[ni][0] - m0);
            s[ni][1] = __expf(s[ni][1] - m0);
            s[ni][2] = __expf(s[ni][2] - m1);
            s[ni][3] = __expf(s[ni][3] - m1);
            ps0 += s[ni][0] + s[ni][1];
            ps1 += s[ni][2] + s[ni][3];
        }
        ps0 = qsum(ps0); ps1 = qsum(ps1);
        l0 = l0 * corr0 + ps0;
        l1 = l1 * corr1 + ps1;
#pragma unroll
        for (int ni = 0; ni < 8; ni++) {
            o[ni][0] *= corr0; o[ni][1] *= corr0;
            o[ni][2] *= corr1; o[ni][3] *= corr1;
        }

        // O += P V: x4.trans loads fragments for ni and ni+1 together
#pragma unroll
        for (int kj = 0; kj < 4; kj++) {
            uint32_t Ah[4], Al[4];
#pragma unroll
            for (int half = 0; half < 2; half++) {
                const int sn = 2 * kj + half;
                const float p0 = s[sn][0], p1 = s[sn][1];
                const float p2 = s[sn][2], p3 = s[sn][3];
                Ah[2 * half + 0] = packbf(p0, p1);
                Ah[2 * half + 1] = packbf(p2, p3);
                Al[2 * half + 0] = packbf(p0 - __bfloat162float(__float2bfloat16(p0)),
                                          p1 - __bfloat162float(__float2bfloat16(p1)));
                Al[2 * half + 1] = packbf(p2 - __bfloat162float(__float2bfloat16(p2)),
                                          p3 - __bfloat162float(__float2bfloat16(p3)));
            }
            const uint32_t vrowb = kb + 2 * ATILE
                                 + (uint32_t)(kj * 16 + vrow16) * SKB;
#pragma unroll
            for (int ni2 = 0; ni2 < 4; ni2++) {
                const uint32_t vd = vrowb + (uint32_t)(2 * ni2 + klane) * 16;
                uint32_t vh4[4], vl4[4];
                ldmat4t(vh4, vd);
                ldmat4t(vl4, vd + ATILE);
                mma16816(o[2 * ni2],     Ah, vh4);
                mma16816(o[2 * ni2],     Ah, vl4);
                mma16816(o[2 * ni2],     Al, vh4);
                mma16816(o[2 * ni2 + 1], Ah, vh4 + 2);
                mma16816(o[2 * ni2 + 1], Ah, vl4 + 2);
                mma16816(o[2 * ni2 + 1], Al, vh4 + 2);
            }
        }
        __syncthreads();
    }

    const float inv0 = 1.f / l0;
    const float inv1 = 1.f / l1;
    const int b = bh >> 4;
    const int h = bh & 15;
    const int r0 = q0 + wm + g;
#pragma unroll
    for (int ni = 0; ni < 8; ni++) {
        const int d = ni * 8 + 2 * tg;
#pragma unroll
        for (int rr = 0; rr < 2; rr++) {
            const int row = r0 + rr * 8;
            const float y0 = o[ni][2 * rr + 0] * (rr ? inv1 : inv0);
            const float y1 = o[ni][2 * rr + 1] * (rr ? inv1 : inv0);
            const size_t off = (size_t)(b * T_LEN + row) * C_DIM + h * D_HEAD + d;
            *(uint32_t*)(g_yhi + off) = packbf(y0, y1);
            *(uint32_t*)(g_ylo + off) =
                packbf(y0 - __bfloat162float(__float2bfloat16(y0)),
                       y1 - __bfloat162float(__float2bfloat16(y1)));
        }
    }
}

// ---------------------------------------------------------------------------
extern "C" void kernel_launch(void* const* d_in, const int* in_sizes, int n_in,
                              void* d_out, int out_size) {
    const float* x  = (const float*)d_in[0];   // (8,1024,1024)
    const float* Wa = (const float*)d_in[1];   // (3072,1024)
    const float* Wp = (const float*)d_in[2];   // (1024,1024)
    float* out = (float*)d_out;                // (8,1024,1024)

    cudaFuncSetAttribute(gemm_mma<0, 128>, cudaFuncAttributeMaxDynamicSharedMemorySize, DSMEM_G);
    cudaFuncSetAttribute(gemm_mma<1, 128>, cudaFuncAttributeMaxDynamicSharedMemorySize, DSMEM_G);
    cudaFuncSetAttribute(attn_mma, cudaFuncAttributeMaxDynamicSharedMemorySize, DSMEM_A);

    __nv_bfloat16 *xhi, *xlo, *wahi, *walo, *wphi, *wplo, *yhi, *ylo;
    cudaGetSymbolAddress((void**)&xhi,  g_xhi);
    cudaGetSymbolAddress((void**)&xlo,  g_xlo);
    cudaGetSymbolAddress((void**)&wahi, g_wahi);
    cudaGetSymbolAddress((void**)&walo, g_walo);
    cudaGetSymbolAddress((void**)&wphi, g_wphi);
    cudaGetSymbolAddress((void**)&wplo, g_wplo);
    cudaGetSymbolAddress((void**)&yhi,  g_yhi);
    cudaGetSymbolAddress((void**)&ylo,  g_ylo);

    split_kernel<<<(M_ROWS * K_DIM / 4) / 256, 256>>>(x,  xhi,  xlo,  M_ROWS * K_DIM / 4);
    split_kernel<<<(3 * C_DIM * K_DIM / 4) / 256, 256>>>(Wa, wahi, walo, 3 * C_DIM * K_DIM / 4);
    split_kernel<<<(C_DIM * K_DIM / 4) / 256, 256>>>(Wp, wphi, wplo, C_DIM * K_DIM / 4);

    gemm_mma<0, 128><<<dim3(3072 / 128, M_ROWS / 128), 256, DSMEM_G>>>(xhi, xlo, wahi, walo, nullptr);

    rotary_kernel<<<(BH * T_LEN) / 256, 256>>>();

    attn_mma<<<dim3(T_LEN / 128, BH), 256, DSMEM_A>>>();

    gemm_mma<1, 128><<<dim3(1024 / 128, M_ROWS / 128), 256, DSMEM_G>>>(yhi, ylo, wphi, wplo, out);
}

// round 11
// speedup vs baseline: 1.0216x; 1.0177x over previous
#include <cuda_runtime.h>
#include <cuda_bf16.h>
#include <math.h>
#include <stdint.h>

// Problem constants
#define B_SZ   8
#define T_LEN  1024
#define C_DIM  1024
#define H_NUM  16
#define D_HEAD 64
#define BH     (B_SZ * H_NUM)        // 128
#define M_ROWS (B_SZ * T_LEN)        // 8192
#define K_DIM  1024

// fp32 scratch (pre-rotary q/k only)
__device__ float g_q[BH * T_LEN * D_HEAD];
__device__ float g_k[BH * T_LEN * D_HEAD];

// bf16 hi/lo split buffers
__device__ __nv_bfloat16 g_xhi[M_ROWS * K_DIM];
__device__ __nv_bfloat16 g_xlo[M_ROWS * K_DIM];
__device__ __nv_bfloat16 g_wahi[3 * C_DIM * K_DIM];
__device__ __nv_bfloat16 g_walo[3 * C_DIM * K_DIM];
__device__ __nv_bfloat16 g_wphi[C_DIM * K_DIM];
__device__ __nv_bfloat16 g_wplo[C_DIM * K_DIM];
__device__ __nv_bfloat16 g_qhi[BH * T_LEN * D_HEAD];
__device__ __nv_bfloat16 g_qlo[BH * T_LEN * D_HEAD];
__device__ __nv_bfloat16 g_khi[BH * T_LEN * D_HEAD];
__device__ __nv_bfloat16 g_klo[BH * T_LEN * D_HEAD];
__device__ __nv_bfloat16 g_vhi[BH * T_LEN * D_HEAD];
__device__ __nv_bfloat16 g_vlo[BH * T_LEN * D_HEAD];
__device__ __nv_bfloat16 g_yhi[M_ROWS * C_DIM];
__device__ __nv_bfloat16 g_ylo[M_ROWS * C_DIM];

// ---------------------------------------------------------------------------
// helpers
// ---------------------------------------------------------------------------
__device__ __forceinline__ uint32_t smem_u32(const void* p) {
    uint32_t a;
    asm("{ .reg .u64 t; cvta.to.shared.u64 t, %1; cvt.u32.u64 %0, t; }"
        : "=r"(a) : "l"(p));
    return a;
}
__device__ __forceinline__ void cp16(uint32_t dst, const void* src) {
    asm volatile("cp.async.cg.shared.global [%0], [%1], 16;" :: "r"(dst), "l"(src));
}
__device__ __forceinline__ void cp_commit() {
    asm volatile("cp.async.commit_group;" ::: "memory");
}
__device__ __forceinline__ void cp_wait1() {
    asm volatile("cp.async.wait_group 1;" ::: "memory");
}
__device__ __forceinline__ void cp_wait0() {
    asm volatile("cp.async.wait_group 0;" ::: "memory");
}
__device__ __forceinline__ void ldmat4(uint32_t* r, uint32_t addr) {
    asm volatile("ldmatrix.sync.aligned.m8n8.x4.shared.b16 {%0,%1,%2,%3}, [%4];"
                 : "=r"(r[0]), "=r"(r[1]), "=r"(r[2]), "=r"(r[3]) : "r"(addr));
}
__device__ __forceinline__ void ldmat2(uint32_t* r, uint32_t addr) {
    asm volatile("ldmatrix.sync.aligned.m8n8.x2.shared.b16 {%0,%1}, [%2];"
                 : "=r"(r[0]), "=r"(r[1]) : "r"(addr));
}
__device__ __forceinline__ void ldmat2t(uint32_t* r, uint32_t addr) {
    asm volatile("ldmatrix.sync.aligned.m8n8.x2.trans.shared.b16 {%0,%1}, [%2];"
                 : "=r"(r[0]), "=r"(r[1]) : "r"(addr));
}
__device__ __forceinline__ void mma16816(float* c, const uint32_t* a, const uint32_t* b) {
    asm volatile(
        "mma.sync.aligned.m16n8k16.row.col.f32.bf16.bf16.f32 "
        "{%0,%1,%2,%3}, {%4,%5,%6,%7}, {%8,%9}, {%0,%1,%2,%3};"
        : "+f"(c[0]), "+f"(c[1]), "+f"(c[2]), "+f"(c[3])
        : "r"(a[0]), "r"(a[1]), "r"(a[2]), "r"(a[3]), "r"(b[0]), "r"(b[1]));
}
__device__ __forceinline__ uint32_t packbf(float a, float b) {
    uint32_t r;
    asm("cvt.rn.bf16x2.f32 %0, %1, %2;" : "=r"(r) : "f"(b), "f"(a));
    return r;
}
__device__ __forceinline__ float qmax(float x) {
    x = fmaxf(x, __shfl_xor_sync(0xffffffffu, x, 1));
    x = fmaxf(x, __shfl_xor_sync(0xffffffffu, x, 2));
    return x;
}
__device__ __forceinline__ float qsum(float x) {
    x += __shfl_xor_sync(0xffffffffu, x, 1);
    x += __shfl_xor_sync(0xffffffffu, x, 2);
    return x;
}

// ---------------------------------------------------------------------------
// fp32 -> (bf16 hi, bf16 lo) split
// ---------------------------------------------------------------------------
__global__ __launch_bounds__(256) void split_kernel(const float* __restrict__ src,
                                                    __nv_bfloat16* __restrict__ hi,
                                                    __nv_bfloat16* __restrict__ lo,
                                                    int n4) {
    int i = blockIdx.x * blockDim.x + threadIdx.x;
    if (i >= n4) return;
    float4 x = ((const float4*)src)[i];
    float xs[4] = {x.x, x.y, x.z, x.w};
    __nv_bfloat16 h[4], l[4];
#pragma unroll
    for (int e = 0; e < 4; e++) {
        h[e] = __float2bfloat16(xs[e]);
        l[e] = __float2bfloat16(xs[e] - __bfloat162float(h[e]));
    }
    ((uint2*)hi)[i] = *(uint2*)h;
    ((uint2*)lo)[i] = *(uint2*)l;
}

// ---------------------------------------------------------------------------
// mma.sync bf16x3 GEMM: BK=32, 80KB smem, 2 CTAs/SM (exact R7-verified kernel)
// ---------------------------------------------------------------------------
#define GSKE 40
#define GSKB (GSKE * 2)              // 80 bytes/row
#define GTILE (128 * GSKB)           // 10240
#define DSMEM (2 * 4 * GTILE)        // 81920

template <int MODE>
__global__ __launch_bounds__(256, 2) void gemm_mma(
    const __nv_bfloat16* __restrict__ Ahi, const __nv_bfloat16* __restrict__ Alo,
    const __nv_bfloat16* __restrict__ Bhi, const __nv_bfloat16* __restrict__ Blo,
    float* __restrict__ Cout) {
    extern __shared__ char dsm[];
    const uint32_t sbase = smem_u32(dsm);

    const int tid  = threadIdx.x;
    const int lane = tid & 31;
    const int wid  = tid >> 5;
    const int wm   = (wid & 1) * 64;
    const int wn   = (wid >> 1) * 32;
    const int bn   = blockIdx.x * 128;
    const int bm   = blockIdx.y * 128;

    float c[4][4][4];
#pragma unroll
    for (int mi = 0; mi < 4; mi++)
#pragma unroll
        for (int ni = 0; ni < 4; ni++)
#pragma unroll
            for (int e = 0; e < 4; e++) c[mi][ni][e] = 0.f;

    const __nv_bfloat16* srcs[4] = {Ahi, Alo, Bhi, Blo};
    const int gbase[2] = {bm, bn};

    auto issue = [&](int ch, int buf) {
        const int k0 = ch * 32;
#pragma unroll
        for (int t = 0; t < 4; t++) {
            const __nv_bfloat16* src = srcs[t];
            const int gb = gbase[t >> 1];
            const uint32_t dbase = sbase + (uint32_t)(buf * 4 + t) * GTILE;
#pragma unroll
            for (int it = 0; it < 2; it++) {
                const int idx = tid + it * 256;
                const int row = idx >> 2;
                const int seg = idx & 3;
                cp16(dbase + (uint32_t)row * GSKB + seg * 16,
                     src + (size_t)(gb + row) * K_DIM + k0 + seg * 8);
            }
        }
        cp_commit();
    };

    issue(0, 0);

    const int arow = lane & 15;
    const int acol = (lane >> 4) << 3;
    const int brow = lane & 7;
    const int bcol = ((lane >> 3) & 1) << 3;

    for (int ch = 0; ch < 32; ch++) {
        cp_wait0();
        __syncthreads();
        if (ch < 31) issue(ch + 1, (ch + 1) & 1);

        const uint32_t abase = sbase + (uint32_t)((ch & 1) * 4 + 0) * GTILE;
        const uint32_t bbase = sbase + (uint32_t)((ch & 1) * 4 + 2) * GTILE;

#pragma unroll
        for (int k16 = 0; k16 < 2; k16++) {
            uint32_t bh[4][2], bl[4][2];
#pragma unroll
            for (int ni = 0; ni < 4; ni++) {
                const uint32_t bd = bbase + (uint32_t)(wn + ni * 8 + brow) * GSKB
                                  + (uint32_t)(k16 * 16 + bcol) * 2;
                ldmat2(bh[ni], bd);
                ldmat2(bl[ni], bd + GTILE);
            }
#pragma unroll
            for (int mi = 0; mi < 4; mi++) {
                uint32_t ah[4], al[4];
                const uint32_t ad = abase + (uint32_t)(wm + mi * 16 + arow) * GSKB
                                  + (uint32_t)(k16 * 16 + acol) * 2;
                ldmat4(ah, ad);
                ldmat4(al, ad + GTILE);
#pragma unroll
                for (int ni = 0; ni < 4; ni++) {
                    mma16816(c[mi][ni], ah, bh[ni]);
                    mma16816(c[mi][ni], ah, bl[ni]);
                    mma16816(c[mi][ni], al, bh[ni]);
                }
            }
        }
    }

    const int g  = lane >> 2;
    const int tg = lane & 3;
#pragma unroll
    for (int mi = 0; mi < 4; mi++) {
#pragma unroll
        for (int ni = 0; ni < 4; ni++) {
            const int n = bn + wn + ni * 8 + 2 * tg;
            const int m0r = bm + wm + mi * 16 + g;
            if (MODE == 0) {
                const int part = n >> 10;
                const int cc = n & 1023;
                const int h = cc >> 6;
                const int d = cc & 63;
#pragma unroll
                for (int rr = 0; rr < 2; rr++) {
                    const int m = m0r + rr * 8;
                    const int b = m >> 10;
                    const int t = m & 1023;
                    const size_t off = ((size_t)(b * 16 + h) * T_LEN + t) * D_HEAD + d;
                    float2 v = rr ? make_float2(c[mi][ni][2], c[mi][ni][3])
                                  : make_float2(c[mi][ni][0], c[mi][ni][1]);
                    if (part == 0)      *(float2*)(g_q + off) = v;
                    else if (part == 1) *(float2*)(g_k + off) = v;
                    else {
                        uint32_t hi = packbf(v.x, v.y);
                        float hx = __bfloat162float(__float2bfloat16(v.x));
                        float hy = __bfloat162float(__float2bfloat16(v.y));
                        uint32_t lo = packbf(v.x - hx, v.y - hy);
                        *(uint32_t*)(g_vhi + off) = hi;
                        *(uint32_t*)(g_vlo + off) = lo;
                    }
                }
            } else {
                *(float2*)(Cout + (size_t)m0r * C_DIM + n) =
                    make_float2(c[mi][ni][0], c[mi][ni][1]);
                *(float2*)(Cout + (size_t)(m0r + 8) * C_DIM + n) =
                    make_float2(c[mi][ni][2], c[mi][ni][3]);
            }
        }
    }
}

// ---------------------------------------------------------------------------
// Rotary: fast __sincosf
// ---------------------------------------------------------------------------
__global__ __launch_bounds__(256) void rotary_kernel() {
    const int idx = blockIdx.x * blockDim.x + threadIdx.x;
    if (idx >= BH * T_LEN) return;
    const float* qp = g_q + (size_t)idx * D_HEAD;
    const float* kp = g_k + (size_t)idx * D_HEAD;

    float q[64], k[64];
#pragma unroll
    for (int i = 0; i < 16; i++) {
        ((float4*)q)[i] = ((const float4*)qp)[i];
        ((float4*)k)[i] = ((const float4*)kp)[i];
    }
    uint32_t* qh32 = (uint32_t*)g_qhi + (size_t)idx * 32;
    uint32_t* ql32 = (uint32_t*)g_qlo + (size_t)idx * 32;
    uint32_t* kh32 = (uint32_t*)g_khi + (size_t)idx * 32;
    uint32_t* kl32 = (uint32_t*)g_klo + (size_t)idx * 32;

#pragma unroll
    for (int i = 0; i < 32; i++) {
        float qo[2], ko[2];
#pragma unroll
        for (int e = 0; e < 2; e++) {
            const int d = 2 * i + e;
            float cc, sn;
            __sincosf(q[d], &sn, &cc);
            const float rq = (d < 32) ? -q[2 * d + 1] : q[2 * d - 64];
            const float rk = (d < 32) ? -k[2 * d + 1] : k[2 * d - 64];
            qo[e] = q[d] * cc + rq * sn;
            ko[e] = k[d] * cc + rk * sn;
        }
        qh32[i] = packbf(qo[0], qo[1]);
        ql32[i] = packbf(qo[0] - __bfloat162float(__float2bfloat16(qo[0])),
                         qo[1] - __bfloat162float(__float2bfloat16(qo[1])));
        kh32[i] = packbf(ko[0], ko[1]);
        kl32[i] = packbf(ko[0] - __bfloat162float(__float2bfloat16(ko[0])),
                         ko[1] - __bfloat162float(__float2bfloat16(ko[1])));
    }
}

// ---------------------------------------------------------------------------
// Tensor-core flash attention: 128-key double-tiles -> half the per-iteration
// softmax/sync overhead. Fragment code identical to the verified R7 kernel.
// ---------------------------------------------------------------------------
#define SKB 144
#define KTILE (128 * SKB)            // 18432: one 128x64 bf16 tile
#define KVBUF (4 * KTILE)            // khi,klo,vhi,vlo for 128 keys
#define DSMEM_A (2 * KTILE + 2 * KVBUF)  // 184320 (1 CTA/SM)

__global__ __launch_bounds__(256, 1) void attn_mma() {
    extern __shared__ char dsm[];
    const uint32_t sbase = smem_u32(dsm);
    const uint32_t kvbase = sbase + 2 * KTILE;

    const int tid  = threadIdx.x;
    const int lane = tid & 31;
    const int wid  = tid >> 5;
    const int wm   = wid * 16;
    const int bh   = blockIdx.y;
    const int q0   = blockIdx.x * 128;
    const int nc   = blockIdx.x + 1;          // 128-key chunks

    // stage Q hi/lo
    {
        const __nv_bfloat16* qs[2] = {g_qhi, g_qlo};
#pragma unroll
        for (int it = 0; it < 8; it++) {
            const int idx = tid + it * 256;   // 0..2047
            const int half = idx >> 10;
            const int rem = idx & 1023;
            const int row = rem >> 3;
            const int seg = rem & 7;
            cp16(sbase + (uint32_t)half * KTILE + (uint32_t)row * SKB + seg * 16,
                 qs[half] + ((size_t)(bh * T_LEN + q0 + row) * D_HEAD + seg * 8));
        }
        cp_commit();
    }

    const __nv_bfloat16* kvsrc[4] = {g_khi, g_klo, g_vhi, g_vlo};
    // one chunk = 128 keys: khi/klo/vhi/vlo tiles of 128 rows each
    auto issue_kv = [&](int j0, int buf) {
#pragma unroll
        for (int it = 0; it < 16; it++) {
            const int idx = tid + it * 256;   // 0..4095
            const int sub = idx >> 10;        // 0..3
            const int rem = idx & 1023;
            const int row = rem >> 3;
            const int seg = rem & 7;
            cp16(kvbase + (uint32_t)buf * KVBUF + (uint32_t)sub * KTILE
                     + (uint32_t)row * SKB + seg * 16,
                 kvsrc[sub] + ((size_t)(bh * T_LEN + j0 + row) * D_HEAD + seg * 8));
        }
        cp_commit();
    };

    issue_kv(0, 0);

    float o[8][4];
#pragma unroll
    for (int ni = 0; ni < 8; ni++)
#pragma unroll
        for (int e = 0; e < 4; e++) o[ni][e] = 0.f;
    float m0 = -1e30f, m1 = -1e30f, l0 = 0.f, l1 = 0.f;
    uint32_t qh[4][4], ql[4][4];

    const int g  = lane >> 2;
    const int tg = lane & 3;
    const int brow = lane & 7;
    const int bsel = ((lane >> 3) & 1) * 8;

    for (int c = 0; c < nc; c++) {
        const int j0 = c * 128;
        if (c + 1 < nc) { issue_kv((c + 1) * 128, (c + 1) & 1); cp_wait1(); }
        else            { cp_wait0(); }
        __syncthreads();

        if (c == 0) {
            const int arow = lane & 15;
            const int acol = (lane >> 4) << 3;
#pragma unroll
            for (int k16 = 0; k16 < 4; k16++) {
                const uint32_t ad = sbase + (uint32_t)(wm + arow) * SKB
                                  + (uint32_t)(k16 * 16 + acol) * 2;
                ldmat4(qh[k16], ad);
                ldmat4(ql[k16], ad + KTILE);
            }
        }

        const uint32_t kb = kvbase + (uint32_t)(c & 1) * KVBUF;

        // S = Q K^T over 128 keys (16 ni groups)
        float s[16][4];
#pragma unroll
        for (int ni = 0; ni < 16; ni++) {
#pragma unroll
            for (int e = 0; e < 4; e++) s[ni][e] = 0.f;
#pragma unroll
            for (int k16 = 0; k16 < 4; k16++) {
                const uint32_t bd = kb + (uint32_t)(ni * 8 + brow) * SKB
                                  + (uint32_t)(k16 * 16 + bsel) * 2;
                uint32_t kh[2], kl[2];
                ldmat2(kh, bd);
                ldmat2(kl, bd + KTILE);
                mma16816(s[ni], qh[k16], kh);
                mma16816(s[ni], qh[k16], kl);
                mma16816(s[ni], ql[k16], kh);
            }
        }

        // causal mask: only the last chunk straddles the diagonal (j0 == q0)
        if (c == nc - 1) {
            const int r0 = q0 + wm + g;
#pragma unroll
            for (int ni = 0; ni < 16; ni++) {
                const int cbase = j0 + ni * 8 + 2 * tg;
#pragma unroll
                for (int e = 0; e < 4; e++) {
                    const int col = cbase + (e & 1);
                    const int row = (e < 2) ? r0 : r0 + 8;
                    if (col > row) s[ni][e] = -1e30f;
                }
            }
        }

        // online softmax over 128 columns
        float tm0 = -1e30f, tm1 = -1e30f;
#pragma unroll
        for (int ni = 0; ni < 16; ni++) {
            tm0 = fmaxf(tm0, fmaxf(s[ni][0], s[ni][1]));
            tm1 = fmaxf(tm1, fmaxf(s[ni][2], s[ni][3]));
        }
        tm0 = qmax(tm0); tm1 = qmax(tm1);
        const float mn0 = fmaxf(m0, tm0);
        const float mn1 = fmaxf(m1, tm1);
        const float corr0 = __expf(m0 - mn0);
        const float corr1 = __expf(m1 - mn1);
        m0 = mn0; m1 = mn1;

        float ps0 = 0.f, ps1 = 0.f;
#pragma unroll
        for (int ni = 0; ni < 16; ni++) {
            s[ni][0] = __expf(s[ni][0] - m0);
            s[ni][1] = __expf(s[ni][1] - m0);
            s[ni][2] = __expf(s[ni][2] - m1);
            s[ni][3] = __expf(s[ni][3] - m1);
            ps0 += s[ni][0] + s[ni][1];
            ps1 += s[ni][2] + s[ni][3];
        }
        ps0 = qsum(ps0); ps1 = qsum(ps1);
        l0 = l0 * corr0 + ps0;
        l1 = l1 * corr1 + ps1;
#pragma unroll
        for (int ni = 0; ni < 8; ni++) {
            o[ni][0] *= corr0; o[ni][1] *= corr0;
            o[ni][2] *= corr1; o[ni][3] *= corr1;
        }

        // O += P V over 128 keys (8 kj groups of 16)
#pragma unroll
        for (int kj = 0; kj < 8; kj++) {
            uint32_t Ah[4], Al[4];
#pragma unroll
            for (int half = 0; half < 2; half++) {
                const int sn = 2 * kj + half;
                const float p0 = s[sn][0], p1 = s[sn][1];
                const float p2 = s[sn][2], p3 = s[sn][3];
                Ah[2 * half + 0] = packbf(p0, p1);
                Ah[2 * half + 1] = packbf(p2, p3);
                Al[2 * half + 0] = packbf(p0 - __bfloat162float(__float2bfloat16(p0)),
                                          p1 - __bfloat162float(__float2bfloat16(p1)));
                Al[2 * half + 1] = packbf(p2 - __bfloat162float(__float2bfloat16(p2)),
                                          p3 - __bfloat162float(__float2bfloat16(p3)));
            }
            const int vrow = kj * 16 + bsel + brow;
#pragma unroll
            for (int ni = 0; ni < 8; ni++) {
                const uint32_t vd = kb + 2 * KTILE + (uint32_t)vrow * SKB + ni * 16;
                uint32_t vh[2], vl[2];
                ldmat2t(vh, vd);
                ldmat2t(vl, vd + KTILE);
                mma16816(o[ni], Ah, vh);
                mma16816(o[ni], Ah, vl);
                mma16816(o[ni], Al, vh);
            }
        }
        __syncthreads();
    }

    const float inv0 = 1.f / l0;
    const float inv1 = 1.f / l1;
    const int b = bh >> 4;
    const int h = bh & 15;
    const int r0 = q0 + wm + g;
#pragma unroll
    for (int ni = 0; ni < 8; ni++) {
        const int d = ni * 8 + 2 * tg;
#pragma unroll
        for (int rr = 0; rr < 2; rr++) {
            const int row = r0 + rr * 8;
            const float y0 = o[ni][2 * rr + 0] * (rr ? inv1 : inv0);
            const float y1 = o[ni][2 * rr + 1] * (rr ? inv1 : inv0);
            const size_t off = (size_t)(b * T_LEN + row) * C_DIM + h * D_HEAD + d;
            *(uint32_t*)(g_yhi + off) = packbf(y0, y1);
            *(uint32_t*)(g_ylo + off) =
                packbf(y0 - __bfloat162float(__float2bfloat16(y0)),
                       y1 - __bfloat162float(__float2bfloat16(y1)));
        }
    }
}

// ---------------------------------------------------------------------------
extern "C" void kernel_launch(void* const* d_in, const int* in_sizes, int n_in,
                              void* d_out, int out_size) {
    const float* x  = (const float*)d_in[0];   // (8,1024,1024)
    const float* Wa = (const float*)d_in[1];   // (3072,1024)
    const float* Wp = (const float*)d_in[2];   // (1024,1024)
    float* out = (float*)d_out;                // (8,1024,1024)

    cudaFuncSetAttribute(gemm_mma<0>, cudaFuncAttributeMaxDynamicSharedMemorySize, DSMEM);
    cudaFuncSetAttribute(gemm_mma<1>, cudaFuncAttributeMaxDynamicSharedMemorySize, DSMEM);
    cudaFuncSetAttribute(attn_mma, cudaFuncAttributeMaxDynamicSharedMemorySize, DSMEM_A);

    __nv_bfloat16 *xhi, *xlo, *wahi, *walo, *wphi, *wplo, *yhi, *ylo;
    cudaGetSymbolAddress((void**)&xhi,  g_xhi);
    cudaGetSymbolAddress((void**)&xlo,  g_xlo);
    cudaGetSymbolAddress((void**)&wahi, g_wahi);
    cudaGetSymbolAddress((void**)&walo, g_walo);
    cudaGetSymbolAddress((void**)&wphi, g_wphi);
    cudaGetSymbolAddress((void**)&wplo, g_wplo);
    cudaGetSymbolAddress((void**)&yhi,  g_yhi);
    cudaGetSymbolAddress((void**)&ylo,  g_ylo);

    split_kernel<<<(M_ROWS * K_DIM / 4) / 256, 256>>>(x,  xhi,  xlo,  M_ROWS * K_DIM / 4);
    split_kernel<<<(3 * C_DIM * K_DIM / 4) / 256, 256>>>(Wa, wahi, walo, 3 * C_DIM * K_DIM / 4);
    split_kernel<<<(C_DIM * K_DIM / 4) / 256, 256>>>(Wp, wphi, wplo, C_DIM * K_DIM / 4);

    gemm_mma<0><<<dim3(3072 / 128, M_ROWS / 128), 256, DSMEM>>>(xhi, xlo, wahi, walo, nullptr);

    rotary_kernel<<<(BH * T_LEN) / 256, 256>>>();

    attn_mma<<<dim3(T_LEN / 128, BH), 256, DSMEM_A>>>();

    gemm_mma<1><<<dim3(1024 / 128, M_ROWS / 128), 256, DSMEM>>>(yhi, ylo, wphi, wplo, out);
}

// round 12
// speedup vs baseline: 1.1160x; 1.0924x over previous
#include <cuda_runtime.h>
#include <cuda_bf16.h>
#include <cuda_fp16.h>
#include <math.h>
#include <stdint.h>

// Problem constants
#define B_SZ   8
#define T_LEN  1024
#define C_DIM  1024
#define H_NUM  16
#define D_HEAD 64
#define BH     (B_SZ * H_NUM)        // 128
#define M_ROWS (B_SZ * T_LEN)        // 8192
#define K_DIM  1024

// fp32 scratch (pre-rotary q/k only)
__device__ float g_q[BH * T_LEN * D_HEAD];
__device__ float g_k[BH * T_LEN * D_HEAD];

// 16-bit buffers (bf16 for x/Wa/q/k paths; fp16 payload for v/y/Wp paths)
__device__ __nv_bfloat16 g_xhi[M_ROWS * K_DIM];
__device__ __nv_bfloat16 g_xlo[M_ROWS * K_DIM];
__device__ __nv_bfloat16 g_wahi[3 * C_DIM * K_DIM];
__device__ __nv_bfloat16 g_walo[3 * C_DIM * K_DIM];
__device__ __nv_bfloat16 g_wph[C_DIM * K_DIM];          // fp16 payload
__device__ __nv_bfloat16 g_qhi[BH * T_LEN * D_HEAD];
__device__ __nv_bfloat16 g_qlo[BH * T_LEN * D_HEAD];
__device__ __nv_bfloat16 g_khi[BH * T_LEN * D_HEAD];
__device__ __nv_bfloat16 g_klo[BH * T_LEN * D_HEAD];
__device__ __nv_bfloat16 g_vhi[BH * T_LEN * D_HEAD];    // fp16 payload
__device__ __nv_bfloat16 g_vlo[BH * T_LEN * D_HEAD];    // fp16 payload
__device__ __nv_bfloat16 g_yhi[M_ROWS * C_DIM];         // fp16 payload
__device__ __nv_bfloat16 g_ylo[M_ROWS * C_DIM];         // fp16 payload

// ---------------------------------------------------------------------------
// helpers
// ---------------------------------------------------------------------------
__device__ __forceinline__ uint32_t smem_u32(const void* p) {
    uint32_t a;
    asm("{ .reg .u64 t; cvta.to.shared.u64 t, %1; cvt.u32.u64 %0, t; }"
        : "=r"(a) : "l"(p));
    return a;
}
__device__ __forceinline__ void cp16(uint32_t dst, const void* src) {
    asm volatile("cp.async.cg.shared.global [%0], [%1], 16;" :: "r"(dst), "l"(src));
}
__device__ __forceinline__ void cp_commit() {
    asm volatile("cp.async.commit_group;" ::: "memory");
}
__device__ __forceinline__ void cp_wait1() {
    asm volatile("cp.async.wait_group 1;" ::: "memory");
}
__device__ __forceinline__ void cp_wait0() {
    asm volatile("cp.async.wait_group 0;" ::: "memory");
}
__device__ __forceinline__ void ldmat4(uint32_t* r, uint32_t addr) {
    asm volatile("ldmatrix.sync.aligned.m8n8.x4.shared.b16 {%0,%1,%2,%3}, [%4];"
                 : "=r"(r[0]), "=r"(r[1]), "=r"(r[2]), "=r"(r[3]) : "r"(addr));
}
__device__ __forceinline__ void ldmat2(uint32_t* r, uint32_t addr) {
    asm volatile("ldmatrix.sync.aligned.m8n8.x2.shared.b16 {%0,%1}, [%2];"
                 : "=r"(r[0]), "=r"(r[1]) : "r"(addr));
}
__device__ __forceinline__ void ldmat2t(uint32_t* r, uint32_t addr) {
    asm volatile("ldmatrix.sync.aligned.m8n8.x2.trans.shared.b16 {%0,%1}, [%2];"
                 : "=r"(r[0]), "=r"(r[1]) : "r"(addr));
}
// bf16 MMA (fp32 accum)
__device__ __forceinline__ void mma16816(float* c, const uint32_t* a, const uint32_t* b) {
    asm volatile(
        "mma.sync.aligned.m16n8k16.row.col.f32.bf16.bf16.f32 "
        "{%0,%1,%2,%3}, {%4,%5,%6,%7}, {%8,%9}, {%0,%1,%2,%3};"
        : "+f"(c[0]), "+f"(c[1]), "+f"(c[2]), "+f"(c[3])
        : "r"(a[0]), "r"(a[1]), "r"(a[2]), "r"(a[3]), "r"(b[0]), "r"(b[1]));
}
// fp16 MMA (fp32 accum)
__device__ __forceinline__ void mma16816h(float* c, const uint32_t* a, const uint32_t* b) {
    asm volatile(
        "mma.sync.aligned.m16n8k16.row.col.f32.f16.f16.f32 "
        "{%0,%1,%2,%3}, {%4,%5,%6,%7}, {%8,%9}, {%0,%1,%2,%3};"
        : "+f"(c[0]), "+f"(c[1]), "+f"(c[2]), "+f"(c[3])
        : "r"(a[0]), "r"(a[1]), "r"(a[2]), "r"(a[3]), "r"(b[0]), "r"(b[1]));
}
__device__ __forceinline__ uint32_t packbf(float a, float b) {
    uint32_t r;
    asm("cvt.rn.bf16x2.f32 %0, %1, %2;" : "=r"(r) : "f"(b), "f"(a));
    return r;
}
__device__ __forceinline__ uint32_t packh(float a, float b) {
    uint32_t r;
    asm("cvt.rn.f16x2.f32 %0, %1, %2;" : "=r"(r) : "f"(b), "f"(a));
    return r;
}
__device__ __forceinline__ float qmax(float x) {
    x = fmaxf(x, __shfl_xor_sync(0xffffffffu, x, 1));
    x = fmaxf(x, __shfl_xor_sync(0xffffffffu, x, 2));
    return x;
}
__device__ __forceinline__ float qsum(float x) {
    x += __shfl_xor_sync(0xffffffffu, x, 1);
    x += __shfl_xor_sync(0xffffffffu, x, 2);
    return x;
}

// ---------------------------------------------------------------------------
// fp32 -> (bf16 hi, bf16 lo) split
// ---------------------------------------------------------------------------
__global__ __launch_bounds__(256) void split_kernel(const float* __restrict__ src,
                                                    __nv_bfloat16* __restrict__ hi,
                                                    __nv_bfloat16* __restrict__ lo,
                                                    int n4) {
    int i = blockIdx.x * blockDim.x + threadIdx.x;
    if (i >= n4) return;
    float4 x = ((const float4*)src)[i];
    float xs[4] = {x.x, x.y, x.z, x.w};
    __nv_bfloat16 h[4], l[4];
#pragma unroll
    for (int e = 0; e < 4; e++) {
        h[e] = __float2bfloat16(xs[e]);
        l[e] = __float2bfloat16(xs[e] - __bfloat162float(h[e]));
    }
    ((uint2*)hi)[i] = *(uint2*)h;
    ((uint2*)lo)[i] = *(uint2*)l;
}

// fp32 -> fp16 (single) convert, for Wp
__global__ __launch_bounds__(256) void half_kernel(const float* __restrict__ src,
                                                   __nv_bfloat16* __restrict__ dst,
                                                   int n4) {
    int i = blockIdx.x * blockDim.x + threadIdx.x;
    if (i >= n4) return;
    float4 x = ((const float4*)src)[i];
    uint2 out;
    out.x = packh(x.x, x.y);
    out.y = packh(x.z, x.w);
    ((uint2*)dst)[i] = out;
}

// ---------------------------------------------------------------------------
// QKV GEMM (bf16x3): BK=32, 80KB smem, 2 CTAs/SM — verified R7 kernel;
// epilogue: q,k fp32 head-layout; v -> fp16 hi/lo head-layout.
// ---------------------------------------------------------------------------
#define GSKE 40
#define GSKB (GSKE * 2)              // 80 bytes/row
#define GTILE (128 * GSKB)           // 10240
#define DSMEM (2 * 4 * GTILE)        // 81920

__global__ __launch_bounds__(256, 2) void gemm_qkv(
    const __nv_bfloat16* __restrict__ Ahi, const __nv_bfloat16* __restrict__ Alo,
    const __nv_bfloat16* __restrict__ Bhi, const __nv_bfloat16* __restrict__ Blo) {
    extern __shared__ char dsm[];
    const uint32_t sbase = smem_u32(dsm);

    const int tid  = threadIdx.x;
    const int lane = tid & 31;
    const int wid  = tid >> 5;
    const int wm   = (wid & 1) * 64;
    const int wn   = (wid >> 1) * 32;
    const int bn   = blockIdx.x * 128;
    const int bm   = blockIdx.y * 128;

    float c[4][4][4];
#pragma unroll
    for (int mi = 0; mi < 4; mi++)
#pragma unroll
        for (int ni = 0; ni < 4; ni++)
#pragma unroll
            for (int e = 0; e < 4; e++) c[mi][ni][e] = 0.f;

    const __nv_bfloat16* srcs[4] = {Ahi, Alo, Bhi, Blo};
    const int gbase[2] = {bm, bn};

    auto issue = [&](int ch, int buf) {
        const int k0 = ch * 32;
#pragma unroll
        for (int t = 0; t < 4; t++) {
            const __nv_bfloat16* src = srcs[t];
            const int gb = gbase[t >> 1];
            const uint32_t dbase = sbase + (uint32_t)(buf * 4 + t) * GTILE;
#pragma unroll
            for (int it = 0; it < 2; it++) {
                const int idx = tid + it * 256;
                const int row = idx >> 2;
                const int seg = idx & 3;
                cp16(dbase + (uint32_t)row * GSKB + seg * 16,
                     src + (size_t)(gb + row) * K_DIM + k0 + seg * 8);
            }
        }
        cp_commit();
    };

    issue(0, 0);

    const int arow = lane & 15;
    const int acol = (lane >> 4) << 3;
    const int brow = lane & 7;
    const int bcol = ((lane >> 3) & 1) << 3;

    for (int ch = 0; ch < 32; ch++) {
        cp_wait0();
        __syncthreads();
        if (ch < 31) issue(ch + 1, (ch + 1) & 1);

        const uint32_t abase = sbase + (uint32_t)((ch & 1) * 4 + 0) * GTILE;
        const uint32_t bbase = sbase + (uint32_t)((ch & 1) * 4 + 2) * GTILE;

#pragma unroll
        for (int k16 = 0; k16 < 2; k16++) {
            uint32_t bh[4][2], bl[4][2];
#pragma unroll
            for (int ni = 0; ni < 4; ni++) {
                const uint32_t bd = bbase + (uint32_t)(wn + ni * 8 + brow) * GSKB
                                  + (uint32_t)(k16 * 16 + bcol) * 2;
                ldmat2(bh[ni], bd);
                ldmat2(bl[ni], bd + GTILE);
            }
#pragma unroll
            for (int mi = 0; mi < 4; mi++) {
                uint32_t ah[4], al[4];
                const uint32_t ad = abase + (uint32_t)(wm + mi * 16 + arow) * GSKB
                                  + (uint32_t)(k16 * 16 + acol) * 2;
                ldmat4(ah, ad);
                ldmat4(al, ad + GTILE);
#pragma unroll
                for (int ni = 0; ni < 4; ni++) {
                    mma16816(c[mi][ni], ah, bh[ni]);
                    mma16816(c[mi][ni], ah, bl[ni]);
                    mma16816(c[mi][ni], al, bh[ni]);
                }
            }
        }
    }

    const int g  = lane >> 2;
    const int tg = lane & 3;
#pragma unroll
    for (int mi = 0; mi < 4; mi++) {
#pragma unroll
        for (int ni = 0; ni < 4; ni++) {
            const int n = bn + wn + ni * 8 + 2 * tg;
            const int m0r = bm + wm + mi * 16 + g;
            const int part = n >> 10;
            const int cc = n & 1023;
            const int h = cc >> 6;
            const int d = cc & 63;
#pragma unroll
            for (int rr = 0; rr < 2; rr++) {
                const int m = m0r + rr * 8;
                const int b = m >> 10;
                const int t = m & 1023;
                const size_t off = ((size_t)(b * 16 + h) * T_LEN + t) * D_HEAD + d;
                float2 v = rr ? make_float2(c[mi][ni][2], c[mi][ni][3])
                              : make_float2(c[mi][ni][0], c[mi][ni][1]);
                if (part == 0)      *(float2*)(g_q + off) = v;
                else if (part == 1) *(float2*)(g_k + off) = v;
                else {
                    // v -> fp16 hi/lo
                    uint32_t hi = packh(v.x, v.y);
                    float hx = __half2float(__float2half(v.x));
                    float hy = __half2float(__float2half(v.y));
                    uint32_t lo = packh(v.x - hx, v.y - hy);
                    *(uint32_t*)(g_vhi + off) = hi;
                    *(uint32_t*)(g_vlo + off) = lo;
                }
            }
        }
    }
}

// ---------------------------------------------------------------------------
// Projection GEMM (fp16, 2 terms): out = (yh + yl) * Wp^T, Wp single fp16.
// smem: {Ahi, Alo, B} x 2 bufs = 61440 -> 2 CTAs/SM.
// ---------------------------------------------------------------------------
#define PBUF (3 * GTILE)             // 30720
#define DSMEM_P (2 * PBUF)           // 61440

__global__ __launch_bounds__(256, 2) void gemm_proj(
    const __nv_bfloat16* __restrict__ Ahi, const __nv_bfloat16* __restrict__ Alo,
    const __nv_bfloat16* __restrict__ B, float* __restrict__ Cout) {
    extern __shared__ char dsm[];
    const uint32_t sbase = smem_u32(dsm);

    const int tid  = threadIdx.x;
    const int lane = tid & 31;
    const int wid  = tid >> 5;
    const int wm   = (wid & 1) * 64;
    const int wn   = (wid >> 1) * 32;
    const int bn   = blockIdx.x * 128;
    const int bm   = blockIdx.y * 128;

    float c[4][4][4];
#pragma unroll
    for (int mi = 0; mi < 4; mi++)
#pragma unroll
        for (int ni = 0; ni < 4; ni++)
#pragma unroll
            for (int e = 0; e < 4; e++) c[mi][ni][e] = 0.f;

    const __nv_bfloat16* srcs[3] = {Ahi, Alo, B};
    const int gbase[3] = {bm, bm, bn};

    auto issue = [&](int ch, int buf) {
        const int k0 = ch * 32;
        const uint32_t bb = sbase + (uint32_t)buf * PBUF;
#pragma unroll
        for (int it = 0; it < 6; it++) {
            const int idx = tid + it * 256;   // 0..1535
            const int t = idx >> 9;           // 0..2
            const int rem = idx & 511;
            const int row = rem >> 2;
            const int seg = rem & 3;
            cp16(bb + (uint32_t)t * GTILE + (uint32_t)row * GSKB + seg * 16,
                 srcs[t] + (size_t)(gbase[t] + row) * K_DIM + k0 + seg * 8);
        }
        cp_commit();
    };

    issue(0, 0);

    const int arow = lane & 15;
    const int acol = (lane >> 4) << 3;
    const int brow = lane & 7;
    const int bcol = ((lane >> 3) & 1) << 3;

    for (int ch = 0; ch < 32; ch++) {
        cp_wait0();
        __syncthreads();
        if (ch < 31) issue(ch + 1, (ch + 1) & 1);

        const uint32_t bb = sbase + (uint32_t)(ch & 1) * PBUF;
        const uint32_t abase = bb;
        const uint32_t bbase = bb + 2 * GTILE;

#pragma unroll
        for (int k16 = 0; k16 < 2; k16++) {
            uint32_t bw[4][2];
#pragma unroll
            for (int ni = 0; ni < 4; ni++) {
                const uint32_t bd = bbase + (uint32_t)(wn + ni * 8 + brow) * GSKB
                                  + (uint32_t)(k16 * 16 + bcol) * 2;
                ldmat2(bw[ni], bd);
            }
#pragma unroll
            for (int mi = 0; mi < 4; mi++) {
                uint32_t ah[4], al[4];
                const uint32_t ad = abase + (uint32_t)(wm + mi * 16 + arow) * GSKB
                                  + (uint32_t)(k16 * 16 + acol) * 2;
                ldmat4(ah, ad);
                ldmat4(al, ad + GTILE);
#pragma unroll
                for (int ni = 0; ni < 4; ni++) {
                    mma16816h(c[mi][ni], ah, bw[ni]);
                    mma16816h(c[mi][ni], al, bw[ni]);
                }
            }
        }
    }

    const int g  = lane >> 2;
    const int tg = lane & 3;
#pragma unroll
    for (int mi = 0; mi < 4; mi++) {
#pragma unroll
        for (int ni = 0; ni < 4; ni++) {
            const int n = bn + wn + ni * 8 + 2 * tg;
            const int m0r = bm + wm + mi * 16 + g;
            *(float2*)(Cout + (size_t)m0r * C_DIM + n) =
                make_float2(c[mi][ni][0], c[mi][ni][1]);
            *(float2*)(Cout + (size_t)(m0r + 8) * C_DIM + n) =
                make_float2(c[mi][ni][2], c[mi][ni][3]);
        }
    }
}

// ---------------------------------------------------------------------------
// Rotary: fast __sincosf
// ---------------------------------------------------------------------------
__global__ __launch_bounds__(256) void rotary_kernel() {
    const int idx = blockIdx.x * blockDim.x + threadIdx.x;
    if (idx >= BH * T_LEN) return;
    const float* qp = g_q + (size_t)idx * D_HEAD;
    const float* kp = g_k + (size_t)idx * D_HEAD;

    float q[64], k[64];
#pragma unroll
    for (int i = 0; i < 16; i++) {
        ((float4*)q)[i] = ((const float4*)qp)[i];
        ((float4*)k)[i] = ((const float4*)kp)[i];
    }
    uint32_t* qh32 = (uint32_t*)g_qhi + (size_t)idx * 32;
    uint32_t* ql32 = (uint32_t*)g_qlo + (size_t)idx * 32;
    uint32_t* kh32 = (uint32_t*)g_khi + (size_t)idx * 32;
    uint32_t* kl32 = (uint32_t*)g_klo + (size_t)idx * 32;

#pragma unroll
    for (int i = 0; i < 32; i++) {
        float qo[2], ko[2];
#pragma unroll
        for (int e = 0; e < 2; e++) {
            const int d = 2 * i + e;
            float cc, sn;
            __sincosf(q[d], &sn, &cc);
            const float rq = (d < 32) ? -q[2 * d + 1] : q[2 * d - 64];
            const float rk = (d < 32) ? -k[2 * d + 1] : k[2 * d - 64];
            qo[e] = q[d] * cc + rq * sn;
            ko[e] = k[d] * cc + rk * sn;
        }
        qh32[i] = packbf(qo[0], qo[1]);
        ql32[i] = packbf(qo[0] - __bfloat162float(__float2bfloat16(qo[0])),
                         qo[1] - __bfloat162float(__float2bfloat16(qo[1])));
        kh32[i] = packbf(ko[0], ko[1]);
        kl32[i] = packbf(ko[0] - __bfloat162float(__float2bfloat16(ko[0])),
                         ko[1] - __bfloat162float(__float2bfloat16(ko[1])));
    }
}

// ---------------------------------------------------------------------------
// Tensor-core flash attention, 128-key chunks.
// QK^T: bf16x3 (unchanged). PV: fp16 single-P x fp16 V hi/lo (2 terms).
// Epilogue: y -> fp16 hi/lo for the fp16 projection GEMM.
// ---------------------------------------------------------------------------
#define SKB 144
#define KTILE (128 * SKB)            // 18432
#define KVBUF (4 * KTILE)
#define DSMEM_A (2 * KTILE + 2 * KVBUF)  // 184320 (1 CTA/SM)

__global__ __launch_bounds__(256, 1) void attn_mma() {
    extern __shared__ char dsm[];
    const uint32_t sbase = smem_u32(dsm);
    const uint32_t kvbase = sbase + 2 * KTILE;

    const int tid  = threadIdx.x;
    const int lane = tid & 31;
    const int wid  = tid >> 5;
    const int wm   = wid * 16;
    const int bh   = blockIdx.y;
    const int q0   = blockIdx.x * 128;
    const int nc   = blockIdx.x + 1;

    {
        const __nv_bfloat16* qs[2] = {g_qhi, g_qlo};
#pragma unroll
        for (int it = 0; it < 8; it++) {
            const int idx = tid + it * 256;
            const int half = idx >> 10;
            const int rem = idx & 1023;
            const int row = rem >> 3;
            const int seg = rem & 7;
            cp16(sbase + (uint32_t)half * KTILE + (uint32_t)row * SKB + seg * 16,
                 qs[half] + ((size_t)(bh * T_LEN + q0 + row) * D_HEAD + seg * 8));
        }
        cp_commit();
    }

    const __nv_bfloat16* kvsrc[4] = {g_khi, g_klo, g_vhi, g_vlo};
    auto issue_kv = [&](int j0, int buf) {
#pragma unroll
        for (int it = 0; it < 16; it++) {
            const int idx = tid + it * 256;
            const int sub = idx >> 10;
            const int rem = idx & 1023;
            const int row = rem >> 3;
            const int seg = rem & 7;
            cp16(kvbase + (uint32_t)buf * KVBUF + (uint32_t)sub * KTILE
                     + (uint32_t)row * SKB + seg * 16,
                 kvsrc[sub] + ((size_t)(bh * T_LEN + j0 + row) * D_HEAD + seg * 8));
        }
        cp_commit();
    };

    issue_kv(0, 0);

    float o[8][4];
#pragma unroll
    for (int ni = 0; ni < 8; ni++)
#pragma unroll
        for (int e = 0; e < 4; e++) o[ni][e] = 0.f;
    float m0 = -1e30f, m1 = -1e30f, l0 = 0.f, l1 = 0.f;
    uint32_t qh[4][4], ql[4][4];

    const int g  = lane >> 2;
    const int tg = lane & 3;
    const int brow = lane & 7;
    const int bsel = ((lane >> 3) & 1) * 8;

    for (int c = 0; c < nc; c++) {
        const int j0 = c * 128;
        if (c + 1 < nc) { issue_kv((c + 1) * 128, (c + 1) & 1); cp_wait1(); }
        else            { cp_wait0(); }
        __syncthreads();

        if (c == 0) {
            const int arow = lane & 15;
            const int acol = (lane >> 4) << 3;
#pragma unroll
            for (int k16 = 0; k16 < 4; k16++) {
                const uint32_t ad = sbase + (uint32_t)(wm + arow) * SKB
                                  + (uint32_t)(k16 * 16 + acol) * 2;
                ldmat4(qh[k16], ad);
                ldmat4(ql[k16], ad + KTILE);
            }
        }

        const uint32_t kb = kvbase + (uint32_t)(c & 1) * KVBUF;

        // S = Q K^T (bf16x3)
        float s[16][4];
#pragma unroll
        for (int ni = 0; ni < 16; ni++) {
#pragma unroll
            for (int e = 0; e < 4; e++) s[ni][e] = 0.f;
#pragma unroll
            for (int k16 = 0; k16 < 4; k16++) {
                const uint32_t bd = kb + (uint32_t)(ni * 8 + brow) * SKB
                                  + (uint32_t)(k16 * 16 + bsel) * 2;
                uint32_t kh[2], kl[2];
                ldmat2(kh, bd);
                ldmat2(kl, bd + KTILE);
                mma16816(s[ni], qh[k16], kh);
                mma16816(s[ni], qh[k16], kl);
                mma16816(s[ni], ql[k16], kh);
            }
        }

        if (c == nc - 1) {
            const int r0 = q0 + wm + g;
#pragma unroll
            for (int ni = 0; ni < 16; ni++) {
                const int cbase = j0 + ni * 8 + 2 * tg;
#pragma unroll
                for (int e = 0; e < 4; e++) {
                    const int col = cbase + (e & 1);
                    const int row = (e < 2) ? r0 : r0 + 8;
                    if (col > row) s[ni][e] = -1e30f;
                }
            }
        }

        float tm0 = -1e30f, tm1 = -1e30f;
#pragma unroll
        for (int ni = 0; ni < 16; ni++) {
            tm0 = fmaxf(tm0, fmaxf(s[ni][0], s[ni][1]));
            tm1 = fmaxf(tm1, fmaxf(s[ni][2], s[ni][3]));
        }
        tm0 = qmax(tm0); tm1 = qmax(tm1);
        const float mn0 = fmaxf(m0, tm0);
        const float mn1 = fmaxf(m1, tm1);
        const float corr0 = __expf(m0 - mn0);
        const float corr1 = __expf(m1 - mn1);
        m0 = mn0; m1 = mn1;

        float ps0 = 0.f, ps1 = 0.f;
#pragma unroll
        for (int ni = 0; ni < 16; ni++) {
            s[ni][0] = __expf(s[ni][0] - m0);
            s[ni][1] = __expf(s[ni][1] - m0);
            s[ni][2] = __expf(s[ni][2] - m1);
            s[ni][3] = __expf(s[ni][3] - m1);
            ps0 += s[ni][0] + s[ni][1];
            ps1 += s[ni][2] + s[ni][3];
        }
        ps0 = qsum(ps0); ps1 = qsum(ps1);
        l0 = l0 * corr0 + ps0;
        l1 = l1 * corr1 + ps1;
#pragma unroll
        for (int ni = 0; ni < 8; ni++) {
            o[ni][0] *= corr0; o[ni][1] *= corr0;
            o[ni][2] *= corr1; o[ni][3] *= corr1;
        }

        // O += P V  (P single fp16; V fp16 hi/lo -> 2 MMAs)
#pragma unroll
        for (int kj = 0; kj < 8; kj++) {
            uint32_t Ah[4];
#pragma unroll
            for (int half = 0; half < 2; half++) {
                const int sn = 2 * kj + half;
                Ah[2 * half + 0] = packh(s[sn][0], s[sn][1]);
                Ah[2 * half + 1] = packh(s[sn][2], s[sn][3]);
            }
            const int vrow = kj * 16 + bsel + brow;
#pragma unroll
            for (int ni = 0; ni < 8; ni++) {
                const uint32_t vd = kb + 2 * KTILE + (uint32_t)vrow * SKB + ni * 16;
                uint32_t vh[2], vl[2];
                ldmat2t(vh, vd);
                ldmat2t(vl, vd + KTILE);
                mma16816h(o[ni], Ah, vh);
                mma16816h(o[ni], Ah, vl);
            }
        }
        __syncthreads();
    }

    // epilogue: normalize, write y as fp16 hi/lo (B,T,C layout)
    const float inv0 = 1.f / l0;
    const float inv1 = 1.f / l1;
    const int b = bh >> 4;
    const int h = bh & 15;
    const int r0 = q0 + wm + g;
#pragma unroll
    for (int ni = 0; ni < 8; ni++) {
        const int d = ni * 8 + 2 * tg;
#pragma unroll
        for (int rr = 0; rr < 2; rr++) {
            const int row = r0 + rr * 8;
            const float y0 = o[ni][2 * rr + 0] * (rr ? inv1 : inv0);
            const float y1 = o[ni][2 * rr + 1] * (rr ? inv1 : inv0);
            const size_t off = (size_t)(b * T_LEN + row) * C_DIM + h * D_HEAD + d;
            *(uint32_t*)(g_yhi + off) = packh(y0, y1);
            const float h0 = __half2float(__float2half(y0));
            const float h1 = __half2float(__float2half(y1));
            *(uint32_t*)(g_ylo + off) = packh(y0 - h0, y1 - h1);
        }
    }
}

// ---------------------------------------------------------------------------
extern "C" void kernel_launch(void* const* d_in, const int* in_sizes, int n_in,
                              void* d_out, int out_size) {
    const float* x  = (const float*)d_in[0];   // (8,1024,1024)
    const float* Wa = (const float*)d_in[1];   // (3072,1024)
    const float* Wp = (const float*)d_in[2];   // (1024,1024)
    float* out = (float*)d_out;                // (8,1024,1024)

    cudaFuncSetAttribute(gemm_qkv,  cudaFuncAttributeMaxDynamicSharedMemorySize, DSMEM);
    cudaFuncSetAttribute(gemm_proj, cudaFuncAttributeMaxDynamicSharedMemorySize, DSMEM_P);
    cudaFuncSetAttribute(attn_mma,  cudaFuncAttributeMaxDynamicSharedMemorySize, DSMEM_A);

    __nv_bfloat16 *xhi, *xlo, *wahi, *walo, *wph, *yhi, *ylo;
    cudaGetSymbolAddress((void**)&xhi,  g_xhi);
    cudaGetSymbolAddress((void**)&xlo,  g_xlo);
    cudaGetSymbolAddress((void**)&wahi, g_wahi);
    cudaGetSymbolAddress((void**)&walo, g_walo);
    cudaGetSymbolAddress((void**)&wph,  g_wph);
    cudaGetSymbolAddress((void**)&yhi,  g_yhi);
    cudaGetSymbolAddress((void**)&ylo,  g_ylo);

    // 1) input conversions
    split_kernel<<<(M_ROWS * K_DIM / 4) / 256, 256>>>(x,  xhi,  xlo,  M_ROWS * K_DIM / 4);
    split_kernel<<<(3 * C_DIM * K_DIM / 4) / 256, 256>>>(Wa, wahi, walo, 3 * C_DIM * K_DIM / 4);
    half_kernel<<<(C_DIM * K_DIM / 4) / 256, 256>>>(Wp, wph, C_DIM * K_DIM / 4);

    // 2) QKV GEMM (bf16x3)
    gemm_qkv<<<dim3(3072 / 128, M_ROWS / 128), 256, DSMEM>>>(xhi, xlo, wahi, walo);

    // 3) Rotary
    rotary_kernel<<<(BH * T_LEN) / 256, 256>>>();

    // 4) Flash attention (QK bf16x3, PV fp16 2-term)
    attn_mma<<<dim3(T_LEN / 128, BH), 256, DSMEM_A>>>();

    // 5) Projection GEMM (fp16 2-term)
    gemm_proj<<<dim3(1024 / 128, M_ROWS / 128), 256, DSMEM_P>>>(yhi, ylo, wph, out);
}

// round 13
// speedup vs baseline: 1.1244x; 1.0075x over previous
#include <cuda_runtime.h>
#include <cuda_bf16.h>
#include <cuda_fp16.h>
#include <math.h>
#include <stdint.h>

// Problem constants
#define B_SZ   8
#define T_LEN  1024
#define C_DIM  1024
#define H_NUM  16
#define D_HEAD 64
#define BH     (B_SZ * H_NUM)        // 128
#define M_ROWS (B_SZ * T_LEN)        // 8192
#define K_DIM  1024

// fp32 scratch (pre-rotary q/k only)
__device__ float g_q[BH * T_LEN * D_HEAD];
__device__ float g_k[BH * T_LEN * D_HEAD];

// 16-bit buffers (payload dtype noted; arrays typed bf16 for storage only)
__device__ __nv_bfloat16 g_xhi[M_ROWS * K_DIM];         // fp16 payload
__device__ __nv_bfloat16 g_xlo[M_ROWS * K_DIM];         // fp16 payload
__device__ __nv_bfloat16 g_wahi[3 * C_DIM * K_DIM];     // fp16 payload
__device__ __nv_bfloat16 g_walo[3 * C_DIM * K_DIM];     // fp16 payload
__device__ __nv_bfloat16 g_wph[C_DIM * K_DIM];          // fp16 payload
__device__ __nv_bfloat16 g_qhi[BH * T_LEN * D_HEAD];    // bf16
__device__ __nv_bfloat16 g_qlo[BH * T_LEN * D_HEAD];    // bf16
__device__ __nv_bfloat16 g_khi[BH * T_LEN * D_HEAD];    // bf16
__device__ __nv_bfloat16 g_klo[BH * T_LEN * D_HEAD];    // bf16
__device__ __nv_bfloat16 g_vhi[BH * T_LEN * D_HEAD];    // fp16 payload
__device__ __nv_bfloat16 g_vlo[BH * T_LEN * D_HEAD];    // fp16 payload
__device__ __nv_bfloat16 g_yhi[M_ROWS * C_DIM];         // fp16 payload
__device__ __nv_bfloat16 g_ylo[M_ROWS * C_DIM];         // fp16 payload

// ---------------------------------------------------------------------------
// helpers
// ---------------------------------------------------------------------------
__device__ __forceinline__ uint32_t smem_u32(const void* p) {
    uint32_t a;
    asm("{ .reg .u64 t; cvta.to.shared.u64 t, %1; cvt.u32.u64 %0, t; }"
        : "=r"(a) : "l"(p));
    return a;
}
__device__ __forceinline__ void cp16(uint32_t dst, const void* src) {
    asm volatile("cp.async.cg.shared.global [%0], [%1], 16;" :: "r"(dst), "l"(src));
}
__device__ __forceinline__ void cp_commit() {
    asm volatile("cp.async.commit_group;" ::: "memory");
}
__device__ __forceinline__ void cp_wait1() {
    asm volatile("cp.async.wait_group 1;" ::: "memory");
}
__device__ __forceinline__ void cp_wait0() {
    asm volatile("cp.async.wait_group 0;" ::: "memory");
}
__device__ __forceinline__ void ldmat4(uint32_t* r, uint32_t addr) {
    asm volatile("ldmatrix.sync.aligned.m8n8.x4.shared.b16 {%0,%1,%2,%3}, [%4];"
                 : "=r"(r[0]), "=r"(r[1]), "=r"(r[2]), "=r"(r[3]) : "r"(addr));
}
__device__ __forceinline__ void ldmat2(uint32_t* r, uint32_t addr) {
    asm volatile("ldmatrix.sync.aligned.m8n8.x2.shared.b16 {%0,%1}, [%2];"
                 : "=r"(r[0]), "=r"(r[1]) : "r"(addr));
}
__device__ __forceinline__ void ldmat2t(uint32_t* r, uint32_t addr) {
    asm volatile("ldmatrix.sync.aligned.m8n8.x2.trans.shared.b16 {%0,%1}, [%2];"
                 : "=r"(r[0]), "=r"(r[1]) : "r"(addr));
}
// bf16 MMA (fp32 accum)
__device__ __forceinline__ void mma16816(float* c, const uint32_t* a, const uint32_t* b) {
    asm volatile(
        "mma.sync.aligned.m16n8k16.row.col.f32.bf16.bf16.f32 "
        "{%0,%1,%2,%3}, {%4,%5,%6,%7}, {%8,%9}, {%0,%1,%2,%3};"
        : "+f"(c[0]), "+f"(c[1]), "+f"(c[2]), "+f"(c[3])
        : "r"(a[0]), "r"(a[1]), "r"(a[2]), "r"(a[3]), "r"(b[0]), "r"(b[1]));
}
// fp16 MMA (fp32 accum)
__device__ __forceinline__ void mma16816h(float* c, const uint32_t* a, const uint32_t* b) {
    asm volatile(
        "mma.sync.aligned.m16n8k16.row.col.f32.f16.f16.f32 "
        "{%0,%1,%2,%3}, {%4,%5,%6,%7}, {%8,%9}, {%0,%1,%2,%3};"
        : "+f"(c[0]), "+f"(c[1]), "+f"(c[2]), "+f"(c[3])
        : "r"(a[0]), "r"(a[1]), "r"(a[2]), "r"(a[3]), "r"(b[0]), "r"(b[1]));
}
__device__ __forceinline__ uint32_t packbf(float a, float b) {
    uint32_t r;
    asm("cvt.rn.bf16x2.f32 %0, %1, %2;" : "=r"(r) : "f"(b), "f"(a));
    return r;
}
__device__ __forceinline__ uint32_t packh(float a, float b) {
    uint32_t r;
    asm("cvt.rn.f16x2.f32 %0, %1, %2;" : "=r"(r) : "f"(b), "f"(a));
    return r;
}
__device__ __forceinline__ float qmax(float x) {
    x = fmaxf(x, __shfl_xor_sync(0xffffffffu, x, 1));
    x = fmaxf(x, __shfl_xor_sync(0xffffffffu, x, 2));
    return x;
}
__device__ __forceinline__ float qsum(float x) {
    x += __shfl_xor_sync(0xffffffffu, x, 1);
    x += __shfl_xor_sync(0xffffffffu, x, 2);
    return x;
}

// ---------------------------------------------------------------------------
// fp32 -> (fp16 hi, fp16 lo) split
// ---------------------------------------------------------------------------
__global__ __launch_bounds__(256) void hsplit_kernel(const float* __restrict__ src,
                                                     __nv_bfloat16* __restrict__ hi,
                                                     __nv_bfloat16* __restrict__ lo,
                                                     int n4) {
    int i = blockIdx.x * blockDim.x + threadIdx.x;
    if (i >= n4) return;
    float4 x = ((const float4*)src)[i];
    float xs[4] = {x.x, x.y, x.z, x.w};
    float hs[4];
#pragma unroll
    for (int e = 0; e < 4; e++) hs[e] = __half2float(__float2half(xs[e]));
    uint2 ho, lv;
    ho.x = packh(xs[0], xs[1]);           // rn-rounded fp16 of x
    ho.y = packh(xs[2], xs[3]);
    lv.x = packh(xs[0] - hs[0], xs[1] - hs[1]);
    lv.y = packh(xs[2] - hs[2], xs[3] - hs[3]);
    ((uint2*)hi)[i] = ho;
    ((uint2*)lo)[i] = lv;
}

// fp32 -> fp16 (single) convert, for Wp
__global__ __launch_bounds__(256) void half_kernel(const float* __restrict__ src,
                                                   __nv_bfloat16* __restrict__ dst,
                                                   int n4) {
    int i = blockIdx.x * blockDim.x + threadIdx.x;
    if (i >= n4) return;
    float4 x = ((const float4*)src)[i];
    uint2 out;
    out.x = packh(x.x, x.y);
    out.y = packh(x.z, x.w);
    ((uint2*)dst)[i] = out;
}

// ---------------------------------------------------------------------------
// QKV GEMM (fp16): BK=32, 2 CTAs/SM.
// q,k columns (bn<2048): 3 terms xh*Wh + xl*Wh + xh*Wl  (error ~2^-24)
// v columns  (bn>=2048): 2 terms (xh+xl)*Wh             (error ~1.4e-4, direct)
// Epilogue: q,k fp32 head-layout; v -> fp16 hi/lo head-layout.
// ---------------------------------------------------------------------------
#define GSKE 40
#define GSKB (GSKE * 2)              // 80 bytes/row
#define GTILE (128 * GSKB)           // 10240
#define DSMEM (2 * 4 * GTILE)        // 81920

__global__ __launch_bounds__(256, 2) void gemm_qkv(
    const __nv_bfloat16* __restrict__ Ahi, const __nv_bfloat16* __restrict__ Alo,
    const __nv_bfloat16* __restrict__ Bhi, const __nv_bfloat16* __restrict__ Blo) {
    extern __shared__ char dsm[];
    const uint32_t sbase = smem_u32(dsm);

    const int tid  = threadIdx.x;
    const int lane = tid & 31;
    const int wid  = tid >> 5;
    const int wm   = (wid & 1) * 64;
    const int wn   = (wid >> 1) * 32;
    const int bn   = blockIdx.x * 128;
    const int bm   = blockIdx.y * 128;
    const bool qk  = (bn < 2048);    // uniform over the CTA

    float c[4][4][4];
#pragma unroll
    for (int mi = 0; mi < 4; mi++)
#pragma unroll
        for (int ni = 0; ni < 4; ni++)
#pragma unroll
            for (int e = 0; e < 4; e++) c[mi][ni][e] = 0.f;

    const __nv_bfloat16* srcs[4] = {Ahi, Alo, Bhi, Blo};
    const int gbase[2] = {bm, bn};

    auto issue = [&](int ch, int buf) {
        const int k0 = ch * 32;
#pragma unroll
        for (int t = 0; t < 4; t++) {
            if (t == 3 && !qk) continue;   // v-CTAs never read Wl
            const __nv_bfloat16* src = srcs[t];
            const int gb = gbase[t >> 1];
            const uint32_t dbase = sbase + (uint32_t)(buf * 4 + t) * GTILE;
#pragma unroll
            for (int it = 0; it < 2; it++) {
                const int idx = tid + it * 256;
                const int row = idx >> 2;
                const int seg = idx & 3;
                cp16(dbase + (uint32_t)row * GSKB + seg * 16,
                     src + (size_t)(gb + row) * K_DIM + k0 + seg * 8);
            }
        }
        cp_commit();
    };

    issue(0, 0);

    const int arow = lane & 15;
    const int acol = (lane >> 4) << 3;
    const int brow = lane & 7;
    const int bcol = ((lane >> 3) & 1) << 3;

    for (int ch = 0; ch < 32; ch++) {
        cp_wait0();
        __syncthreads();
        if (ch < 31) issue(ch + 1, (ch + 1) & 1);

        const uint32_t abase = sbase + (uint32_t)((ch & 1) * 4 + 0) * GTILE;
        const uint32_t bbase = sbase + (uint32_t)((ch & 1) * 4 + 2) * GTILE;

#pragma unroll
        for (int k16 = 0; k16 < 2; k16++) {
            uint32_t bh[4][2], bl[4][2];
#pragma unroll
            for (int ni = 0; ni < 4; ni++) {
                const uint32_t bd = bbase + (uint32_t)(wn + ni * 8 + brow) * GSKB
                                  + (uint32_t)(k16 * 16 + bcol) * 2;
                ldmat2(bh[ni], bd);
                if (qk) ldmat2(bl[ni], bd + GTILE);
            }
#pragma unroll
            for (int mi = 0; mi < 4; mi++) {
                uint32_t ah[4], al[4];
                const uint32_t ad = abase + (uint32_t)(wm + mi * 16 + arow) * GSKB
                                  + (uint32_t)(k16 * 16 + acol) * 2;
                ldmat4(ah, ad);
                ldmat4(al, ad + GTILE);
#pragma unroll
                for (int ni = 0; ni < 4; ni++) {
                    mma16816h(c[mi][ni], ah, bh[ni]);
                    mma16816h(c[mi][ni], al, bh[ni]);
                    if (qk) mma16816h(c[mi][ni], ah, bl[ni]);
                }
            }
        }
    }

    const int g  = lane >> 2;
    const int tg = lane & 3;
#pragma unroll
    for (int mi = 0; mi < 4; mi++) {
#pragma unroll
        for (int ni = 0; ni < 4; ni++) {
            const int n = bn + wn + ni * 8 + 2 * tg;
            const int m0r = bm + wm + mi * 16 + g;
            const int part = n >> 10;
            const int cc = n & 1023;
            const int h = cc >> 6;
            const int d = cc & 63;
#pragma unroll
            for (int rr = 0; rr < 2; rr++) {
                const int m = m0r + rr * 8;
                const int b = m >> 10;
                const int t = m & 1023;
                const size_t off = ((size_t)(b * 16 + h) * T_LEN + t) * D_HEAD + d;
                float2 v = rr ? make_float2(c[mi][ni][2], c[mi][ni][3])
                              : make_float2(c[mi][ni][0], c[mi][ni][1]);
                if (part == 0)      *(float2*)(g_q + off) = v;
                else if (part == 1) *(float2*)(g_k + off) = v;
                else {
                    uint32_t hi = packh(v.x, v.y);
                    float hx = __half2float(__float2half(v.x));
                    float hy = __half2float(__float2half(v.y));
                    uint32_t lo = packh(v.x - hx, v.y - hy);
                    *(uint32_t*)(g_vhi + off) = hi;
                    *(uint32_t*)(g_vlo + off) = lo;
                }
            }
        }
    }
}

// ---------------------------------------------------------------------------
// Projection GEMM (fp16, 2 terms): out = (yh + yl) * Wp^T, Wp single fp16.
// ---------------------------------------------------------------------------
#define PBUF (3 * GTILE)             // 30720
#define DSMEM_P (2 * PBUF)           // 61440

__global__ __launch_bounds__(256, 2) void gemm_proj(
    const __nv_bfloat16* __restrict__ Ahi, const __nv_bfloat16* __restrict__ Alo,
    const __nv_bfloat16* __restrict__ B, float* __restrict__ Cout) {
    extern __shared__ char dsm[];
    const uint32_t sbase = smem_u32(dsm);

    const int tid  = threadIdx.x;
    const int lane = tid & 31;
    const int wid  = tid >> 5;
    const int wm   = (wid & 1) * 64;
    const int wn   = (wid >> 1) * 32;
    const int bn   = blockIdx.x * 128;
    const int bm   = blockIdx.y * 128;

    float c[4][4][4];
#pragma unroll
    for (int mi = 0; mi < 4; mi++)
#pragma unroll
        for (int ni = 0; ni < 4; ni++)
#pragma unroll
            for (int e = 0; e < 4; e++) c[mi][ni][e] = 0.f;

    const __nv_bfloat16* srcs[3] = {Ahi, Alo, B};
    const int gbase[3] = {bm, bm, bn};

    auto issue = [&](int ch, int buf) {
        const int k0 = ch * 32;
        const uint32_t bb = sbase + (uint32_t)buf * PBUF;
#pragma unroll
        for (int it = 0; it < 6; it++) {
            const int idx = tid + it * 256;
            const int t = idx >> 9;
            const int rem = idx & 511;
            const int row = rem >> 2;
            const int seg = rem & 3;
            cp16(bb + (uint32_t)t * GTILE + (uint32_t)row * GSKB + seg * 16,
                 srcs[t] + (size_t)(gbase[t] + row) * K_DIM + k0 + seg * 8);
        }
        cp_commit();
    };

    issue(0, 0);

    const int arow = lane & 15;
    const int acol = (lane >> 4) << 3;
    const int brow = lane & 7;
    const int bcol = ((lane >> 3) & 1) << 3;

    for (int ch = 0; ch < 32; ch++) {
        cp_wait0();
        __syncthreads();
        if (ch < 31) issue(ch + 1, (ch + 1) & 1);

        const uint32_t bb = sbase + (uint32_t)(ch & 1) * PBUF;
        const uint32_t abase = bb;
        const uint32_t bbase = bb + 2 * GTILE;

#pragma unroll
        for (int k16 = 0; k16 < 2; k16++) {
            uint32_t bw[4][2];
#pragma unroll
            for (int ni = 0; ni < 4; ni++) {
                const uint32_t bd = bbase + (uint32_t)(wn + ni * 8 + brow) * GSKB
                                  + (uint32_t)(k16 * 16 + bcol) * 2;
                ldmat2(bw[ni], bd);
            }
#pragma unroll
            for (int mi = 0; mi < 4; mi++) {
                uint32_t ah[4], al[4];
                const uint32_t ad = abase + (uint32_t)(wm + mi * 16 + arow) * GSKB
                                  + (uint32_t)(k16 * 16 + acol) * 2;
                ldmat4(ah, ad);
                ldmat4(al, ad + GTILE);
#pragma unroll
                for (int ni = 0; ni < 4; ni++) {
                    mma16816h(c[mi][ni], ah, bw[ni]);
                    mma16816h(c[mi][ni], al, bw[ni]);
                }
            }
        }
    }

    const int g  = lane >> 2;
    const int tg = lane & 3;
#pragma unroll
    for (int mi = 0; mi < 4; mi++) {
#pragma unroll
        for (int ni = 0; ni < 4; ni++) {
            const int n = bn + wn + ni * 8 + 2 * tg;
            const int m0r = bm + wm + mi * 16 + g;
            *(float2*)(Cout + (size_t)m0r * C_DIM + n) =
                make_float2(c[mi][ni][0], c[mi][ni][1]);
            *(float2*)(Cout + (size_t)(m0r + 8) * C_DIM + n) =
                make_float2(c[mi][ni][2], c[mi][ni][3]);
        }
    }
}

// ---------------------------------------------------------------------------
// Rotary: fast __sincosf; outputs bf16 hi/lo of rotated q,k
// ---------------------------------------------------------------------------
__global__ __launch_bounds__(256) void rotary_kernel() {
    const int idx = blockIdx.x * blockDim.x + threadIdx.x;
    if (idx >= BH * T_LEN) return;
    const float* qp = g_q + (size_t)idx * D_HEAD;
    const float* kp = g_k + (size_t)idx * D_HEAD;

    float q[64], k[64];
#pragma unroll
    for (int i = 0; i < 16; i++) {
        ((float4*)q)[i] = ((const float4*)qp)[i];
        ((float4*)k)[i] = ((const float4*)kp)[i];
    }
    uint32_t* qh32 = (uint32_t*)g_qhi + (size_t)idx * 32;
    uint32_t* ql32 = (uint32_t*)g_qlo + (size_t)idx * 32;
    uint32_t* kh32 = (uint32_t*)g_khi + (size_t)idx * 32;
    uint32_t* kl32 = (uint32_t*)g_klo + (size_t)idx * 32;

#pragma unroll
    for (int i = 0; i < 32; i++) {
        float qo[2], ko[2];
#pragma unroll
        for (int e = 0; e < 2; e++) {
            const int d = 2 * i + e;
            float cc, sn;
            __sincosf(q[d], &sn, &cc);
            const float rq = (d < 32) ? -q[2 * d + 1] : q[2 * d - 64];
            const float rk = (d < 32) ? -k[2 * d + 1] : k[2 * d - 64];
            qo[e] = q[d] * cc + rq * sn;
            ko[e] = k[d] * cc + rk * sn;
        }
        qh32[i] = packbf(qo[0], qo[1]);
        ql32[i] = packbf(qo[0] - __bfloat162float(__float2bfloat16(qo[0])),
                         qo[1] - __bfloat162float(__float2bfloat16(qo[1])));
        kh32[i] = packbf(ko[0], ko[1]);
        kl32[i] = packbf(ko[0] - __bfloat162float(__float2bfloat16(ko[0])),
                         ko[1] - __bfloat162float(__float2bfloat16(ko[1])));
    }
}

// ---------------------------------------------------------------------------
// Tensor-core flash attention, 128-key chunks.
// QK^T: bf16x3. PV: fp16 single-P x fp16 V hi/lo (2 terms). (verified R12)
// ---------------------------------------------------------------------------
#define SKB 144
#define KTILE (128 * SKB)            // 18432
#define KVBUF (4 * KTILE)
#define DSMEM_A (2 * KTILE + 2 * KVBUF)  // 184320 (1 CTA/SM)

__global__ __launch_bounds__(256, 1) void attn_mma() {
    extern __shared__ char dsm[];
    const uint32_t sbase = smem_u32(dsm);
    const uint32_t kvbase = sbase + 2 * KTILE;

    const int tid  = threadIdx.x;
    const int lane = tid & 31;
    const int wid  = tid >> 5;
    const int wm   = wid * 16;
    const int bh   = blockIdx.y;
    const int q0   = blockIdx.x * 128;
    const int nc   = blockIdx.x + 1;

    {
        const __nv_bfloat16* qs[2] = {g_qhi, g_qlo};
#pragma unroll
        for (int it = 0; it < 8; it++) {
            const int idx = tid + it * 256;
            const int half = idx >> 10;
            const int rem = idx & 1023;
            const int row = rem >> 3;
            const int seg = rem & 7;
            cp16(sbase + (uint32_t)half * KTILE + (uint32_t)row * SKB + seg * 16,
                 qs[half] + ((size_t)(bh * T_LEN + q0 + row) * D_HEAD + seg * 8));
        }
        cp_commit();
    }

    const __nv_bfloat16* kvsrc[4] = {g_khi, g_klo, g_vhi, g_vlo};
    auto issue_kv = [&](int j0, int buf) {
#pragma unroll
        for (int it = 0; it < 16; it++) {
            const int idx = tid + it * 256;
            const int sub = idx >> 10;
            const int rem = idx & 1023;
            const int row = rem >> 3;
            const int seg = rem & 7;
            cp16(kvbase + (uint32_t)buf * KVBUF + (uint32_t)sub * KTILE
                     + (uint32_t)row * SKB + seg * 16,
                 kvsrc[sub] + ((size_t)(bh * T_LEN + j0 + row) * D_HEAD + seg * 8));
        }
        cp_commit();
    };

    issue_kv(0, 0);

    float o[8][4];
#pragma unroll
    for (int ni = 0; ni < 8; ni++)
#pragma unroll
        for (int e = 0; e < 4; e++) o[ni][e] = 0.f;
    float m0 = -1e30f, m1 = -1e30f, l0 = 0.f, l1 = 0.f;
    uint32_t qh[4][4], ql[4][4];

    const int g  = lane >> 2;
    const int tg = lane & 3;
    const int brow = lane & 7;
    const int bsel = ((lane >> 3) & 1) * 8;

    for (int c = 0; c < nc; c++) {
        const int j0 = c * 128;
        if (c + 1 < nc) { issue_kv((c + 1) * 128, (c + 1) & 1); cp_wait1(); }
        else            { cp_wait0(); }
        __syncthreads();

        if (c == 0) {
            const int arow = lane & 15;
            const int acol = (lane >> 4) << 3;
#pragma unroll
            for (int k16 = 0; k16 < 4; k16++) {
                const uint32_t ad = sbase + (uint32_t)(wm + arow) * SKB
                                  + (uint32_t)(k16 * 16 + acol) * 2;
                ldmat4(qh[k16], ad);
                ldmat4(ql[k16], ad + KTILE);
            }
        }

        const uint32_t kb = kvbase + (uint32_t)(c & 1) * KVBUF;

        float s[16][4];
#pragma unroll
        for (int ni = 0; ni < 16; ni++) {
#pragma unroll
            for (int e = 0; e < 4; e++) s[ni][e] = 0.f;
#pragma unroll
            for (int k16 = 0; k16 < 4; k16++) {
                const uint32_t bd = kb + (uint32_t)(ni * 8 + brow) * SKB
                                  + (uint32_t)(k16 * 16 + bsel) * 2;
                uint32_t kh[2], kl[2];
                ldmat2(kh, bd);
                ldmat2(kl, bd + KTILE);
                mma16816(s[ni], qh[k16], kh);
                mma16816(s[ni], qh[k16], kl);
                mma16816(s[ni], ql[k16], kh);
            }
        }

        if (c == nc - 1) {
            const int r0 = q0 + wm + g;
#pragma unroll
            for (int ni = 0; ni < 16; ni++) {
                const int cbase = j0 + ni * 8 + 2 * tg;
#pragma unroll
                for (int e = 0; e < 4; e++) {
                    const int col = cbase + (e & 1);
                    const int row = (e < 2) ? r0 : r0 + 8;
                    if (col > row) s[ni][e] = -1e30f;
                }
            }
        }

        float tm0 = -1e30f, tm1 = -1e30f;
#pragma unroll
        for (int ni = 0; ni < 16; ni++) {
            tm0 = fmaxf(tm0, fmaxf(s[ni][0], s[ni][1]));
            tm1 = fmaxf(tm1, fmaxf(s[ni][2], s[ni][3]));
        }
        tm0 = qmax(tm0); tm1 = qmax(tm1);
        const float mn0 = fmaxf(m0, tm0);
        const float mn1 = fmaxf(m1, tm1);
        const float corr0 = __expf(m0 - mn0);
        const float corr1 = __expf(m1 - mn1);
        m0 = mn0; m1 = mn1;

        float ps0 = 0.f, ps1 = 0.f;
#pragma unroll
        for (int ni = 0; ni < 16; ni++) {
            s[ni][0] = __expf(s[ni][0] - m0);
            s[ni][1] = __expf(s[ni][1] - m0);
            s[ni][2] = __expf(s[ni][2] - m1);
            s[ni][3] = __expf(s[ni][3] - m1);
            ps0 += s[ni][0] + s[ni][1];
            ps1 += s[ni][2] + s[ni][3];
        }
        ps0 = qsum(ps0); ps1 = qsum(ps1);
        l0 = l0 * corr0 + ps0;
        l1 = l1 * corr1 + ps1;
#pragma unroll
        for (int ni = 0; ni < 8; ni++) {
            o[ni][0] *= corr0; o[ni][1] *= corr0;
            o[ni][2] *= corr1; o[ni][3] *= corr1;
        }

#pragma unroll
        for (int kj = 0; kj < 8; kj++) {
            uint32_t Ah[4];
#pragma unroll
            for (int half = 0; half < 2; half++) {
                const int sn = 2 * kj + half;
                Ah[2 * half + 0] = packh(s[sn][0], s[sn][1]);
                Ah[2 * half + 1] = packh(s[sn][2], s[sn][3]);
            }
            const int vrow = kj * 16 + bsel + brow;
#pragma unroll
            for (int ni = 0; ni < 8; ni++) {
                const uint32_t vd = kb + 2 * KTILE + (uint32_t)vrow * SKB + ni * 16;
                uint32_t vh[2], vl[2];
                ldmat2t(vh, vd);
                ldmat2t(vl, vd + KTILE);
                mma16816h(o[ni], Ah, vh);
                mma16816h(o[ni], Ah, vl);
            }
        }
        __syncthreads();
    }

    const float inv0 = 1.f / l0;
    const float inv1 = 1.f / l1;
    const int b = bh >> 4;
    const int h = bh & 15;
    const int r0 = q0 + wm + g;
#pragma unroll
    for (int ni = 0; ni < 8; ni++) {
        const int d = ni * 8 + 2 * tg;
#pragma unroll
        for (int rr = 0; rr < 2; rr++) {
            const int row = r0 + rr * 8;
            const float y0 = o[ni][2 * rr + 0] * (rr ? inv1 : inv0);
            const float y1 = o[ni][2 * rr + 1] * (rr ? inv1 : inv0);
            const size_t off = (size_t)(b * T_LEN + row) * C_DIM + h * D_HEAD + d;
            *(uint32_t*)(g_yhi + off) = packh(y0, y1);
            const float h0 = __half2float(__float2half(y0));
            const float h1 = __half2float(__float2half(y1));
            *(uint32_t*)(g_ylo + off) = packh(y0 - h0, y1 - h1);
        }
    }
}

// ---------------------------------------------------------------------------
extern "C" void kernel_launch(void* const* d_in, const int* in_sizes, int n_in,
                              void* d_out, int out_size) {
    const float* x  = (const float*)d_in[0];   // (8,1024,1024)
    const float* Wa = (const float*)d_in[1];   // (3072,1024)
    const float* Wp = (const float*)d_in[2];   // (1024,1024)
    float* out = (float*)d_out;                // (8,1024,1024)

    cudaFuncSetAttribute(gemm_qkv,  cudaFuncAttributeMaxDynamicSharedMemorySize, DSMEM);
    cudaFuncSetAttribute(gemm_proj, cudaFuncAttributeMaxDynamicSharedMemorySize, DSMEM_P);
    cudaFuncSetAttribute(attn_mma,  cudaFuncAttributeMaxDynamicSharedMemorySize, DSMEM_A);

    __nv_bfloat16 *xhi, *xlo, *wahi, *walo, *wph, *yhi, *ylo;
    cudaGetSymbolAddress((void**)&xhi,  g_xhi);
    cudaGetSymbolAddress((void**)&xlo,  g_xlo);
    cudaGetSymbolAddress((void**)&wahi, g_wahi);
    cudaGetSymbolAddress((void**)&walo, g_walo);
    cudaGetSymbolAddress((void**)&wph,  g_wph);
    cudaGetSymbolAddress((void**)&yhi,  g_yhi);
    cudaGetSymbolAddress((void**)&ylo,  g_ylo);

    // 1) input conversions (fp16 hi/lo splits)
    hsplit_kernel<<<(M_ROWS * K_DIM / 4) / 256, 256>>>(x,  xhi,  xlo,  M_ROWS * K_DIM / 4);
    hsplit_kernel<<<(3 * C_DIM * K_DIM / 4) / 256, 256>>>(Wa, wahi, walo, 3 * C_DIM * K_DIM / 4);
    half_kernel<<<(C_DIM * K_DIM / 4) / 256, 256>>>(Wp, wph, C_DIM * K_DIM / 4);

    // 2) QKV GEMM (fp16; 3-term for q,k columns, 2-term for v columns)
    gemm_qkv<<<dim3(3072 / 128, M_ROWS / 128), 256, DSMEM>>>(xhi, xlo, wahi, walo);

    // 3) Rotary
    rotary_kernel<<<(BH * T_LEN) / 256, 256>>>();

    // 4) Flash attention (QK bf16x3, PV fp16 2-term)
    attn_mma<<<dim3(T_LEN / 128, BH), 256, DSMEM_A>>>();

    // 5) Projection GEMM (fp16 2-term)
    gemm_proj<<<dim3(1024 / 128, M_ROWS / 128), 256, DSMEM_P>>>(yhi, ylo, wph, out);
}

// round 14
// speedup vs baseline: 1.2375x; 1.1006x over previous
#include <cuda_runtime.h>
#include <cuda_bf16.h>
#include <cuda_fp16.h>
#include <math.h>
#include <stdint.h>

// Problem constants
#define B_SZ   8
#define T_LEN  1024
#define C_DIM  1024
#define H_NUM  16
#define D_HEAD 64
#define BH     (B_SZ * H_NUM)        // 128
#define M_ROWS (B_SZ * T_LEN)        // 8192
#define K_DIM  1024

// fp32 scratch (pre-rotary q/k only)
__device__ float g_q[BH * T_LEN * D_HEAD];
__device__ float g_k[BH * T_LEN * D_HEAD];

// 16-bit buffers (payload dtype noted; arrays typed bf16 for storage only)
__device__ __nv_bfloat16 g_xhi[M_ROWS * K_DIM];         // fp16 payload
__device__ __nv_bfloat16 g_xlo[M_ROWS * K_DIM];         // fp16 payload
__device__ __nv_bfloat16 g_wahi[3 * C_DIM * K_DIM];     // fp16 payload
__device__ __nv_bfloat16 g_walo[3 * C_DIM * K_DIM];     // fp16 payload
__device__ __nv_bfloat16 g_wph[C_DIM * K_DIM];          // fp16 payload
__device__ __nv_bfloat16 g_qhi[BH * T_LEN * D_HEAD];    // bf16
__device__ __nv_bfloat16 g_qlo[BH * T_LEN * D_HEAD];    // bf16
__device__ __nv_bfloat16 g_khi[BH * T_LEN * D_HEAD];    // bf16
__device__ __nv_bfloat16 g_klo[BH * T_LEN * D_HEAD];    // bf16
__device__ __nv_bfloat16 g_vhi[BH * T_LEN * D_HEAD];    // fp16 payload (single)
__device__ __nv_bfloat16 g_yhi[M_ROWS * C_DIM];         // fp16 payload (single)

// ---------------------------------------------------------------------------
// helpers
// ---------------------------------------------------------------------------
__device__ __forceinline__ uint32_t smem_u32(const void* p) {
    uint32_t a;
    asm("{ .reg .u64 t; cvta.to.shared.u64 t, %1; cvt.u32.u64 %0, t; }"
        : "=r"(a) : "l"(p));
    return a;
}
__device__ __forceinline__ void cp16(uint32_t dst, const void* src) {
    asm volatile("cp.async.cg.shared.global [%0], [%1], 16;" :: "r"(dst), "l"(src));
}
__device__ __forceinline__ void cp_commit() {
    asm volatile("cp.async.commit_group;" ::: "memory");
}
__device__ __forceinline__ void cp_wait1() {
    asm volatile("cp.async.wait_group 1;" ::: "memory");
}
__device__ __forceinline__ void cp_wait0() {
    asm volatile("cp.async.wait_group 0;" ::: "memory");
}
__device__ __forceinline__ void ldmat4(uint32_t* r, uint32_t addr) {
    asm volatile("ldmatrix.sync.aligned.m8n8.x4.shared.b16 {%0,%1,%2,%3}, [%4];"
                 : "=r"(r[0]), "=r"(r[1]), "=r"(r[2]), "=r"(r[3]) : "r"(addr));
}
__device__ __forceinline__ void ldmat2(uint32_t* r, uint32_t addr) {
    asm volatile("ldmatrix.sync.aligned.m8n8.x2.shared.b16 {%0,%1}, [%2];"
                 : "=r"(r[0]), "=r"(r[1]) : "r"(addr));
}
__device__ __forceinline__ void ldmat2t(uint32_t* r, uint32_t addr) {
    asm volatile("ldmatrix.sync.aligned.m8n8.x2.trans.shared.b16 {%0,%1}, [%2];"
                 : "=r"(r[0]), "=r"(r[1]) : "r"(addr));
}
// bf16 MMA (fp32 accum)
__device__ __forceinline__ void mma16816(float* c, const uint32_t* a, const uint32_t* b) {
    asm volatile(
        "mma.sync.aligned.m16n8k16.row.col.f32.bf16.bf16.f32 "
        "{%0,%1,%2,%3}, {%4,%5,%6,%7}, {%8,%9}, {%0,%1,%2,%3};"
        : "+f"(c[0]), "+f"(c[1]), "+f"(c[2]), "+f"(c[3])
        : "r"(a[0]), "r"(a[1]), "r"(a[2]), "r"(a[3]), "r"(b[0]), "r"(b[1]));
}
// fp16 MMA (fp32 accum)
__device__ __forceinline__ void mma16816h(float* c, const uint32_t* a, const uint32_t* b) {
    asm volatile(
        "mma.sync.aligned.m16n8k16.row.col.f32.f16.f16.f32 "
        "{%0,%1,%2,%3}, {%4,%5,%6,%7}, {%8,%9}, {%0,%1,%2,%3};"
        : "+f"(c[0]), "+f"(c[1]), "+f"(c[2]), "+f"(c[3])
        : "r"(a[0]), "r"(a[1]), "r"(a[2]), "r"(a[3]), "r"(b[0]), "r"(b[1]));
}
__device__ __forceinline__ uint32_t packbf(float a, float b) {
    uint32_t r;
    asm("cvt.rn.bf16x2.f32 %0, %1, %2;" : "=r"(r) : "f"(b), "f"(a));
    return r;
}
__device__ __forceinline__ uint32_t packh(float a, float b) {
    uint32_t r;
    asm("cvt.rn.f16x2.f32 %0, %1, %2;" : "=r"(r) : "f"(b), "f"(a));
    return r;
}
__device__ __forceinline__ float qmax(float x) {
    x = fmaxf(x, __shfl_xor_sync(0xffffffffu, x, 1));
    x = fmaxf(x, __shfl_xor_sync(0xffffffffu, x, 2));
    return x;
}
__device__ __forceinline__ float qsum(float x) {
    x += __shfl_xor_sync(0xffffffffu, x, 1);
    x += __shfl_xor_sync(0xffffffffu, x, 2);
    return x;
}

// ---------------------------------------------------------------------------
// fp32 -> (fp16 hi, fp16 lo) split
// ---------------------------------------------------------------------------
__global__ __launch_bounds__(256) void hsplit_kernel(const float* __restrict__ src,
                                                     __nv_bfloat16* __restrict__ hi,
                                                     __nv_bfloat16* __restrict__ lo,
                                                     int n4) {
    int i = blockIdx.x * blockDim.x + threadIdx.x;
    if (i >= n4) return;
    float4 x = ((const float4*)src)[i];
    float xs[4] = {x.x, x.y, x.z, x.w};
    float hs[4];
#pragma unroll
    for (int e = 0; e < 4; e++) hs[e] = __half2float(__float2half(xs[e]));
    uint2 ho, lv;
    ho.x = packh(xs[0], xs[1]);
    ho.y = packh(xs[2], xs[3]);
    lv.x = packh(xs[0] - hs[0], xs[1] - hs[1]);
    lv.y = packh(xs[2] - hs[2], xs[3] - hs[3]);
    ((uint2*)hi)[i] = ho;
    ((uint2*)lo)[i] = lv;
}

// fp32 -> fp16 (single) convert, for Wp
__global__ __launch_bounds__(256) void half_kernel(const float* __restrict__ src,
                                                   __nv_bfloat16* __restrict__ dst,
                                                   int n4) {
    int i = blockIdx.x * blockDim.x + threadIdx.x;
    if (i >= n4) return;
    float4 x = ((const float4*)src)[i];
    uint2 out;
    out.x = packh(x.x, x.y);
    out.y = packh(x.z, x.w);
    ((uint2*)dst)[i] = out;
}

// ---------------------------------------------------------------------------
// QKV GEMM (fp16): BK=32, 2 CTAs/SM.
// q,k columns: 3 terms xh*Wh + xl*Wh + xh*Wl; v columns: 2 terms (xh+xl)*Wh.
// Epilogue: q,k fp32 head-layout; v -> single fp16 head-layout.
// ---------------------------------------------------------------------------
#define GSKE 40
#define GSKB (GSKE * 2)              // 80 bytes/row
#define GTILE (128 * GSKB)           // 10240
#define DSMEM (2 * 4 * GTILE)        // 81920

__global__ __launch_bounds__(256, 2) void gemm_qkv(
    const __nv_bfloat16* __restrict__ Ahi, const __nv_bfloat16* __restrict__ Alo,
    const __nv_bfloat16* __restrict__ Bhi, const __nv_bfloat16* __restrict__ Blo) {
    extern __shared__ char dsm[];
    const uint32_t sbase = smem_u32(dsm);

    const int tid  = threadIdx.x;
    const int lane = tid & 31;
    const int wid  = tid >> 5;
    const int wm   = (wid & 1) * 64;
    const int wn   = (wid >> 1) * 32;
    const int bn   = blockIdx.x * 128;
    const int bm   = blockIdx.y * 128;
    const bool qk  = (bn < 2048);

    float c[4][4][4];
#pragma unroll
    for (int mi = 0; mi < 4; mi++)
#pragma unroll
        for (int ni = 0; ni < 4; ni++)
#pragma unroll
            for (int e = 0; e < 4; e++) c[mi][ni][e] = 0.f;

    const __nv_bfloat16* srcs[4] = {Ahi, Alo, Bhi, Blo};
    const int gbase[2] = {bm, bn};

    auto issue = [&](int ch, int buf) {
        const int k0 = ch * 32;
#pragma unroll
        for (int t = 0; t < 4; t++) {
            if (t == 3 && !qk) continue;
            const __nv_bfloat16* src = srcs[t];
            const int gb = gbase[t >> 1];
            const uint32_t dbase = sbase + (uint32_t)(buf * 4 + t) * GTILE;
#pragma unroll
            for (int it = 0; it < 2; it++) {
                const int idx = tid + it * 256;
                const int row = idx >> 2;
                const int seg = idx & 3;
                cp16(dbase + (uint32_t)row * GSKB + seg * 16,
                     src + (size_t)(gb + row) * K_DIM + k0 + seg * 8);
            }
        }
        cp_commit();
    };

    issue(0, 0);

    const int arow = lane & 15;
    const int acol = (lane >> 4) << 3;
    const int brow = lane & 7;
    const int bcol = ((lane >> 3) & 1) << 3;

    for (int ch = 0; ch < 32; ch++) {
        cp_wait0();
        __syncthreads();
        if (ch < 31) issue(ch + 1, (ch + 1) & 1);

        const uint32_t abase = sbase + (uint32_t)((ch & 1) * 4 + 0) * GTILE;
        const uint32_t bbase = sbase + (uint32_t)((ch & 1) * 4 + 2) * GTILE;

#pragma unroll
        for (int k16 = 0; k16 < 2; k16++) {
            uint32_t bh[4][2], bl[4][2];
#pragma unroll
            for (int ni = 0; ni < 4; ni++) {
                const uint32_t bd = bbase + (uint32_t)(wn + ni * 8 + brow) * GSKB
                                  + (uint32_t)(k16 * 16 + bcol) * 2;
                ldmat2(bh[ni], bd);
                if (qk) ldmat2(bl[ni], bd + GTILE);
            }
#pragma unroll
            for (int mi = 0; mi < 4; mi++) {
                uint32_t ah[4], al[4];
                const uint32_t ad = abase + (uint32_t)(wm + mi * 16 + arow) * GSKB
                                  + (uint32_t)(k16 * 16 + acol) * 2;
                ldmat4(ah, ad);
                ldmat4(al, ad + GTILE);
#pragma unroll
                for (int ni = 0; ni < 4; ni++) {
                    mma16816h(c[mi][ni], ah, bh[ni]);
                    mma16816h(c[mi][ni], al, bh[ni]);
                    if (qk) mma16816h(c[mi][ni], ah, bl[ni]);
                }
            }
        }
    }

    const int g  = lane >> 2;
    const int tg = lane & 3;
#pragma unroll
    for (int mi = 0; mi < 4; mi++) {
#pragma unroll
        for (int ni = 0; ni < 4; ni++) {
            const int n = bn + wn + ni * 8 + 2 * tg;
            const int m0r = bm + wm + mi * 16 + g;
            const int part = n >> 10;
            const int cc = n & 1023;
            const int h = cc >> 6;
            const int d = cc & 63;
#pragma unroll
            for (int rr = 0; rr < 2; rr++) {
                const int m = m0r + rr * 8;
                const int b = m >> 10;
                const int t = m & 1023;
                const size_t off = ((size_t)(b * 16 + h) * T_LEN + t) * D_HEAD + d;
                float2 v = rr ? make_float2(c[mi][ni][2], c[mi][ni][3])
                              : make_float2(c[mi][ni][0], c[mi][ni][1]);
                if (part == 0)      *(float2*)(g_q + off) = v;
                else if (part == 1) *(float2*)(g_k + off) = v;
                else                *(uint32_t*)(g_vhi + off) = packh(v.x, v.y);
            }
        }
    }
}

// ---------------------------------------------------------------------------
// Projection GEMM (fp16, 1 term): out = y * Wp^T, y and Wp single fp16.
// ---------------------------------------------------------------------------
#define PBUF (2 * GTILE)             // 20480
#define DSMEM_P (2 * PBUF)           // 40960

__global__ __launch_bounds__(256, 2) void gemm_proj(
    const __nv_bfloat16* __restrict__ A, const __nv_bfloat16* __restrict__ B,
    float* __restrict__ Cout) {
    extern __shared__ char dsm[];
    const uint32_t sbase = smem_u32(dsm);

    const int tid  = threadIdx.x;
    const int lane = tid & 31;
    const int wid  = tid >> 5;
    const int wm   = (wid & 1) * 64;
    const int wn   = (wid >> 1) * 32;
    const int bn   = blockIdx.x * 128;
    const int bm   = blockIdx.y * 128;

    float c[4][4][4];
#pragma unroll
    for (int mi = 0; mi < 4; mi++)
#pragma unroll
        for (int ni = 0; ni < 4; ni++)
#pragma unroll
            for (int e = 0; e < 4; e++) c[mi][ni][e] = 0.f;

    const __nv_bfloat16* srcs[2] = {A, B};
    const int gbase[2] = {bm, bn};

    auto issue = [&](int ch, int buf) {
        const int k0 = ch * 32;
        const uint32_t bb = sbase + (uint32_t)buf * PBUF;
#pragma unroll
        for (int it = 0; it < 4; it++) {
            const int idx = tid + it * 256;   // 0..1023
            const int t = idx >> 9;           // 0..1
            const int rem = idx & 511;
            const int row = rem >> 2;
            const int seg = rem & 3;
            cp16(bb + (uint32_t)t * GTILE + (uint32_t)row * GSKB + seg * 16,
                 srcs[t] + (size_t)(gbase[t] + row) * K_DIM + k0 + seg * 8);
        }
        cp_commit();
    };

    issue(0, 0);

    const int arow = lane & 15;
    const int acol = (lane >> 4) << 3;
    const int brow = lane & 7;
    const int bcol = ((lane >> 3) & 1) << 3;

    for (int ch = 0; ch < 32; ch++) {
        cp_wait0();
        __syncthreads();
        if (ch < 31) issue(ch + 1, (ch + 1) & 1);

        const uint32_t bb = sbase + (uint32_t)(ch & 1) * PBUF;
        const uint32_t abase = bb;
        const uint32_t bbase = bb + GTILE;

#pragma unroll
        for (int k16 = 0; k16 < 2; k16++) {
            uint32_t bw[4][2];
#pragma unroll
            for (int ni = 0; ni < 4; ni++) {
                const uint32_t bd = bbase + (uint32_t)(wn + ni * 8 + brow) * GSKB
                                  + (uint32_t)(k16 * 16 + bcol) * 2;
                ldmat2(bw[ni], bd);
            }
#pragma unroll
            for (int mi = 0; mi < 4; mi++) {
                uint32_t ah[4];
                const uint32_t ad = abase + (uint32_t)(wm + mi * 16 + arow) * GSKB
                                  + (uint32_t)(k16 * 16 + acol) * 2;
                ldmat4(ah, ad);
#pragma unroll
                for (int ni = 0; ni < 4; ni++)
                    mma16816h(c[mi][ni], ah, bw[ni]);
            }
        }
    }

    const int g  = lane >> 2;
    const int tg = lane & 3;
#pragma unroll
    for (int mi = 0; mi < 4; mi++) {
#pragma unroll
        for (int ni = 0; ni < 4; ni++) {
            const int n = bn + wn + ni * 8 + 2 * tg;
            const int m0r = bm + wm + mi * 16 + g;
            *(float2*)(Cout + (size_t)m0r * C_DIM + n) =
                make_float2(c[mi][ni][0], c[mi][ni][1]);
            *(float2*)(Cout + (size_t)(m0r + 8) * C_DIM + n) =
                make_float2(c[mi][ni][2], c[mi][ni][3]);
        }
    }
}

// ---------------------------------------------------------------------------
// Rotary: fast __sincosf; outputs bf16 hi/lo of rotated q,k
// ---------------------------------------------------------------------------
__global__ __launch_bounds__(256) void rotary_kernel() {
    const int idx = blockIdx.x * blockDim.x + threadIdx.x;
    if (idx >= BH * T_LEN) return;
    const float* qp = g_q + (size_t)idx * D_HEAD;
    const float* kp = g_k + (size_t)idx * D_HEAD;

    float q[64], k[64];
#pragma unroll
    for (int i = 0; i < 16; i++) {
        ((float4*)q)[i] = ((const float4*)qp)[i];
        ((float4*)k)[i] = ((const float4*)kp)[i];
    }
    uint32_t* qh32 = (uint32_t*)g_qhi + (size_t)idx * 32;
    uint32_t* ql32 = (uint32_t*)g_qlo + (size_t)idx * 32;
    uint32_t* kh32 = (uint32_t*)g_khi + (size_t)idx * 32;
    uint32_t* kl32 = (uint32_t*)g_klo + (size_t)idx * 32;

#pragma unroll
    for (int i = 0; i < 32; i++) {
        float qo[2], ko[2];
#pragma unroll
        for (int e = 0; e < 2; e++) {
            const int d = 2 * i + e;
            float cc, sn;
            __sincosf(q[d], &sn, &cc);
            const float rq = (d < 32) ? -q[2 * d + 1] : q[2 * d - 64];
            const float rk = (d < 32) ? -k[2 * d + 1] : k[2 * d - 64];
            qo[e] = q[d] * cc + rq * sn;
            ko[e] = k[d] * cc + rk * sn;
        }
        qh32[i] = packbf(qo[0], qo[1]);
        ql32[i] = packbf(qo[0] - __bfloat162float(__float2bfloat16(qo[0])),
                         qo[1] - __bfloat162float(__float2bfloat16(qo[1])));
        kh32[i] = packbf(ko[0], ko[1]);
        kl32[i] = packbf(ko[0] - __bfloat162float(__float2bfloat16(ko[0])),
                         ko[1] - __bfloat162float(__float2bfloat16(ko[1])));
    }
}

// ---------------------------------------------------------------------------
// Tensor-core flash attention, 128-key chunks.
// QK^T: bf16x3. PV: fp16 P x single-fp16 V (1 MMA). KV chunk = 3 tiles.
// Epilogue: y -> single fp16.
// ---------------------------------------------------------------------------
#define SKB 144
#define KTILE (128 * SKB)            // 18432
#define KVBUF (3 * KTILE)            // khi, klo, vhi
#define DSMEM_A (2 * KTILE + 2 * KVBUF)  // 147456 (1 CTA/SM)

__global__ __launch_bounds__(256, 1) void attn_mma() {
    extern __shared__ char dsm[];
    const uint32_t sbase = smem_u32(dsm);
    const uint32_t kvbase = sbase + 2 * KTILE;

    const int tid  = threadIdx.x;
    const int lane = tid & 31;
    const int wid  = tid >> 5;
    const int wm   = wid * 16;
    const int bh   = blockIdx.y;
    const int q0   = blockIdx.x * 128;
    const int nc   = blockIdx.x + 1;

    {
        const __nv_bfloat16* qs[2] = {g_qhi, g_qlo};
#pragma unroll
        for (int it = 0; it < 8; it++) {
            const int idx = tid + it * 256;
            const int half = idx >> 10;
            const int rem = idx & 1023;
            const int row = rem >> 3;
            const int seg = rem & 7;
            cp16(sbase + (uint32_t)half * KTILE + (uint32_t)row * SKB + seg * 16,
                 qs[half] + ((size_t)(bh * T_LEN + q0 + row) * D_HEAD + seg * 8));
        }
        cp_commit();
    }

    const __nv_bfloat16* kvsrc[3] = {g_khi, g_klo, g_vhi};
    auto issue_kv = [&](int j0, int buf) {
#pragma unroll
        for (int it = 0; it < 12; it++) {
            const int idx = tid + it * 256;   // 0..3071
            const int sub = idx >> 10;        // 0..2
            const int rem = idx & 1023;
            const int row = rem >> 3;
            const int seg = rem & 7;
            cp16(kvbase + (uint32_t)buf * KVBUF + (uint32_t)sub * KTILE
                     + (uint32_t)row * SKB + seg * 16,
                 kvsrc[sub] + ((size_t)(bh * T_LEN + j0 + row) * D_HEAD + seg * 8));
        }
        cp_commit();
    };

    issue_kv(0, 0);

    float o[8][4];
#pragma unroll
    for (int ni = 0; ni < 8; ni++)
#pragma unroll
        for (int e = 0; e < 4; e++) o[ni][e] = 0.f;
    float m0 = -1e30f, m1 = -1e30f, l0 = 0.f, l1 = 0.f;
    uint32_t qh[4][4], ql[4][4];

    const int g  = lane >> 2;
    const int tg = lane & 3;
    const int brow = lane & 7;
    const int bsel = ((lane >> 3) & 1) * 8;

    for (int c = 0; c < nc; c++) {
        const int j0 = c * 128;
        if (c + 1 < nc) { issue_kv((c + 1) * 128, (c + 1) & 1); cp_wait1(); }
        else            { cp_wait0(); }
        __syncthreads();

        if (c == 0) {
            const int arow = lane & 15;
            const int acol = (lane >> 4) << 3;
#pragma unroll
            for (int k16 = 0; k16 < 4; k16++) {
                const uint32_t ad = sbase + (uint32_t)(wm + arow) * SKB
                                  + (uint32_t)(k16 * 16 + acol) * 2;
                ldmat4(qh[k16], ad);
                ldmat4(ql[k16], ad + KTILE);
            }
        }

        const uint32_t kb = kvbase + (uint32_t)(c & 1) * KVBUF;

        // S = Q K^T (bf16x3)
        float s[16][4];
#pragma unroll
        for (int ni = 0; ni < 16; ni++) {
#pragma unroll
            for (int e = 0; e < 4; e++) s[ni][e] = 0.f;
#pragma unroll
            for (int k16 = 0; k16 < 4; k16++) {
                const uint32_t bd = kb + (uint32_t)(ni * 8 + brow) * SKB
                                  + (uint32_t)(k16 * 16 + bsel) * 2;
                uint32_t kh[2], kl[2];
                ldmat2(kh, bd);
                ldmat2(kl, bd + KTILE);
                mma16816(s[ni], qh[k16], kh);
                mma16816(s[ni], qh[k16], kl);
                mma16816(s[ni], ql[k16], kh);
            }
        }

        if (c == nc - 1) {
            const int r0 = q0 + wm + g;
#pragma unroll
            for (int ni = 0; ni < 16; ni++) {
                const int cbase = j0 + ni * 8 + 2 * tg;
#pragma unroll
                for (int e = 0; e < 4; e++) {
                    const int col = cbase + (e & 1);
                    const int row = (e < 2) ? r0 : r0 + 8;
                    if (col > row) s[ni][e] = -1e30f;
                }
            }
        }

        float tm0 = -1e30f, tm1 = -1e30f;
#pragma unroll
        for (int ni = 0; ni < 16; ni++) {
            tm0 = fmaxf(tm0, fmaxf(s[ni][0], s[ni][1]));
            tm1 = fmaxf(tm1, fmaxf(s[ni][2], s[ni][3]));
        }
        tm0 = qmax(tm0); tm1 = qmax(tm1);
        const float mn0 = fmaxf(m0, tm0);
        const float mn1 = fmaxf(m1, tm1);
        const float corr0 = __expf(m0 - mn0);
        const float corr1 = __expf(m1 - mn1);
        m0 = mn0; m1 = mn1;

        float ps0 = 0.f, ps1 = 0.f;
#pragma unroll
        for (int ni = 0; ni < 16; ni++) {
            s[ni][0] = __expf(s[ni][0] - m0);
            s[ni][1] = __expf(s[ni][1] - m0);
            s[ni][2] = __expf(s[ni][2] - m1);
            s[ni][3] = __expf(s[ni][3] - m1);
            ps0 += s[ni][0] + s[ni][1];
            ps1 += s[ni][2] + s[ni][3];
        }
        ps0 = qsum(ps0); ps1 = qsum(ps1);
        l0 = l0 * corr0 + ps0;
        l1 = l1 * corr1 + ps1;
#pragma unroll
        for (int ni = 0; ni < 8; ni++) {
            o[ni][0] *= corr0; o[ni][1] *= corr0;
            o[ni][2] *= corr1; o[ni][3] *= corr1;
        }

        // O += P V  (P fp16; V single fp16 -> 1 MMA per fragment)
#pragma unroll
        for (int kj = 0; kj < 8; kj++) {
            uint32_t Ah[4];
#pragma unroll
            for (int half = 0; half < 2; half++) {
                const int sn = 2 * kj + half;
                Ah[2 * half + 0] = packh(s[sn][0], s[sn][1]);
                Ah[2 * half + 1] = packh(s[sn][2], s[sn][3]);
            }
            const int vrow = kj * 16 + bsel + brow;
#pragma unroll
            for (int ni = 0; ni < 8; ni++) {
                const uint32_t vd = kb + 2 * KTILE + (uint32_t)vrow * SKB + ni * 16;
                uint32_t vh[2];
                ldmat2t(vh, vd);
                mma16816h(o[ni], Ah, vh);
            }
        }
        __syncthreads();
    }

    // epilogue: normalize, write y as single fp16 (B,T,C layout)
    const float inv0 = 1.f / l0;
    const float inv1 = 1.f / l1;
    const int b = bh >> 4;
    const int h = bh & 15;
    const int r0 = q0 + wm + g;
#pragma unroll
    for (int ni = 0; ni < 8; ni++) {
        const int d = ni * 8 + 2 * tg;
#pragma unroll
        for (int rr = 0; rr < 2; rr++) {
            const int row = r0 + rr * 8;
            const float y0 = o[ni][2 * rr + 0] * (rr ? inv1 : inv0);
            const float y1 = o[ni][2 * rr + 1] * (rr ? inv1 : inv0);
            const size_t off = (size_t)(b * T_LEN + row) * C_DIM + h * D_HEAD + d;
            *(uint32_t*)(g_yhi + off) = packh(y0, y1);
        }
    }
}

// ---------------------------------------------------------------------------
extern "C" void kernel_launch(void* const* d_in, const int* in_sizes, int n_in,
                              void* d_out, int out_size) {
    const float* x  = (const float*)d_in[0];   // (8,1024,1024)
    const float* Wa = (const float*)d_in[1];   // (3072,1024)
    const float* Wp = (const float*)d_in[2];   // (1024,1024)
    float* out = (float*)d_out;                // (8,1024,1024)

    cudaFuncSetAttribute(gemm_qkv,  cudaFuncAttributeMaxDynamicSharedMemorySize, DSMEM);
    cudaFuncSetAttribute(gemm_proj, cudaFuncAttributeMaxDynamicSharedMemorySize, DSMEM_P);
    cudaFuncSetAttribute(attn_mma,  cudaFuncAttributeMaxDynamicSharedMemorySize, DSMEM_A);

    __nv_bfloat16 *xhi, *xlo, *wahi, *walo, *wph, *yhi;
    cudaGetSymbolAddress((void**)&xhi,  g_xhi);
    cudaGetSymbolAddress((void**)&xlo,  g_xlo);
    cudaGetSymbolAddress((void**)&wahi, g_wahi);
    cudaGetSymbolAddress((void**)&walo, g_walo);
    cudaGetSymbolAddress((void**)&wph,  g_wph);
    cudaGetSymbolAddress((void**)&yhi,  g_yhi);

    // 1) input conversions
    hsplit_kernel<<<(M_ROWS * K_DIM / 4) / 256, 256>>>(x,  xhi,  xlo,  M_ROWS * K_DIM / 4);
    hsplit_kernel<<<(3 * C_DIM * K_DIM / 4) / 256, 256>>>(Wa, wahi, walo, 3 * C_DIM * K_DIM / 4);
    half_kernel<<<(C_DIM * K_DIM / 4) / 256, 256>>>(Wp, wph, C_DIM * K_DIM / 4);

    // 2) QKV GEMM (fp16; 3-term q,k / 2-term v)
    gemm_qkv<<<dim3(3072 / 128, M_ROWS / 128), 256, DSMEM>>>(xhi, xlo, wahi, walo);

    // 3) Rotary
    rotary_kernel<<<(BH * T_LEN) / 256, 256>>>();

    // 4) Flash attention (QK bf16x3, PV fp16 1-term)
    attn_mma<<<dim3(T_LEN / 128, BH), 256, DSMEM_A>>>();

    // 5) Projection GEMM (fp16 1-term)
    gemm_proj<<<dim3(1024 / 128, M_ROWS / 128), 256, DSMEM_P>>>(yhi, wph, out);
}